// round 14
// baseline (speedup 1.0000x reference)
#include <cuda_runtime.h>
#include <cuda_fp16.h>
#include <math.h>

#define BSZ 2
#define LSEQ 1024
#define DMODEL 1024
#define DINNER 2048
#define DSTATE 64
#define NHEADS 32
#define HEADDIM 64
#define CONVCH 2176
#define DPROJ 4256
#define NTOK 2048    // BSZ*LSEQ
#define SSEG 16      // chunks per sequence
#define TSEG 64      // chunk length
#define NPAD_WIN 4352   // 34*128 padded N for input proj weights

typedef unsigned long long u64;
typedef unsigned int u32;

// ---------------- tf32 helpers (ssd_y) -----------------
__device__ __forceinline__ u32 to_tf32(float v) {
    u32 r; asm("cvt.rna.tf32.f32 %0, %1;" : "=r"(r) : "f"(v)); return r;
}
__device__ __forceinline__ void split_tf32(float v, u32& hi, u32& lo) {
    hi = to_tf32(v);
    lo = to_tf32(v - __uint_as_float(hi));
}
__device__ __forceinline__ void mma_tf32(float* d, const u32* a, const u32* b) {
    asm volatile(
        "mma.sync.aligned.m16n8k8.row.col.f32.tf32.tf32.f32 "
        "{%0,%1,%2,%3}, {%4,%5,%6,%7}, {%8,%9}, {%0,%1,%2,%3};"
        : "+f"(d[0]), "+f"(d[1]), "+f"(d[2]), "+f"(d[3])
        : "r"(a[0]), "r"(a[1]), "r"(a[2]), "r"(a[3]), "r"(b[0]), "r"(b[1]));
}

// ---------------- fp16 helpers -----------------
__device__ __forceinline__ uint2 split2_f16(float v0, float v1) {
    __half h0 = __float2half_rn(v0), h1 = __float2half_rn(v1);
    u32 h = ((u32)__half_as_ushort(h1) << 16) | (u32)__half_as_ushort(h0);
    float r0 = v0 - __half2float(h0);
    float r1 = v1 - __half2float(h1);
    __half l0 = __float2half_rn(r0), l1 = __float2half_rn(r1);
    u32 l = ((u32)__half_as_ushort(l1) << 16) | (u32)__half_as_ushort(l0);
    return make_uint2(h, l);
}
__device__ __forceinline__ void mma_f16(float* d, const u32* a, const u32* b) {
    asm volatile(
        "mma.sync.aligned.m16n8k16.row.col.f32.f16.f16.f32 "
        "{%0,%1,%2,%3}, {%4,%5,%6,%7}, {%8,%9}, {%0,%1,%2,%3};"
        : "+f"(d[0]), "+f"(d[1]), "+f"(d[2]), "+f"(d[3])
        : "r"(a[0]), "r"(a[1]), "r"(a[2]), "r"(a[3]), "r"(b[0]), "r"(b[1]));
}

// ---------------- scratch ----------------
__device__ float g_zx[2][(size_t)NTOK * DPROJ];
__device__ float g_xbc[2][(size_t)NTOK * CONVCH];
__device__ float g_dt[2][NTOK * NHEADS];
__device__ float g_dA[2][NTOK * NHEADS];
__device__ float g_cump[2][NTOK * NHEADS];
__device__ float g_y[2][(size_t)NTOK * DINNER];
#define SEGIDX(dir,b,seg,h) ((((size_t)(dir)*BSZ + (b))*SSEG + (seg))*NHEADS + (h))
__device__ float g_hseg[(size_t)2 * BSZ * SSEG * NHEADS * HEADDIM * DSTATE];
__device__ float g_hin [(size_t)2 * BSZ * SSEG * NHEADS * HEADDIM * DSTATE];

// pre-split fp16 pair buffers (uint2 = {hi-pair, lo-pair} per 2 fp32 elems)
__device__ uint2 g_x2[(size_t)NTOK * (DMODEL / 2)];                // A fmt [m][kp]
__device__ uint2 g_fWin2[(size_t)(DMODEL / 2) * NPAD_WIN];         // B fmt [kp][n]
__device__ uint2 g_bWin2[(size_t)(DMODEL / 2) * NPAD_WIN];
__device__ uint2 g_fWout2[(size_t)(DINNER / 2) * DMODEL];
__device__ uint2 g_bWout2[(size_t)(DINNER / 2) * DMODEL];
__device__ uint2 g_Wo2[(size_t)DMODEL * DMODEL];
__device__ uint2 g_gn2[2][(size_t)NTOK * (DINNER / 2)];            // A fmt
__device__ uint2 g_cat2[(size_t)NTOK * DMODEL];                    // A fmt

// ---------------- pre-split kernels ----------------
__global__ __launch_bounds__(256)
void presplitA(const float* __restrict__ in, uint2* __restrict__ out, int total)
{
    int t = (blockIdx.x * 256 + threadIdx.x) * 2;
    if (t >= total) return;
    float4 v = *(const float4*)(in + (size_t)t * 2);
    out[t]     = split2_f16(v.x, v.y);
    out[t + 1] = split2_f16(v.z, v.w);
}
__global__ __launch_bounds__(256)
void presplitB_all(const float* __restrict__ fWin, const float* __restrict__ bWin,
                   const float* __restrict__ fWout, const float* __restrict__ bWout,
                   const float* __restrict__ Wo,
                   uint2* __restrict__ o0, uint2* __restrict__ o1,
                   uint2* __restrict__ o2, uint2* __restrict__ o3,
                   uint2* __restrict__ o4)
{
    const int job = blockIdx.z;
    const int kp = blockIdx.y;
    const int n = blockIdx.x * 256 + threadIdx.x;
    const float* in; uint2* out; int N, Npad, KP;
    switch (job) {
        case 0: in = fWin;  out = o0; N = DPROJ;  Npad = NPAD_WIN; KP = DMODEL / 2; break;
        case 1: in = bWin;  out = o1; N = DPROJ;  Npad = NPAD_WIN; KP = DMODEL / 2; break;
        case 2: in = fWout; out = o2; N = DMODEL; Npad = DMODEL;   KP = DINNER / 2; break;
        case 3: in = bWout; out = o3; N = DMODEL; Npad = DMODEL;   KP = DINNER / 2; break;
        default: in = Wo;   out = o4; N = DMODEL; Npad = DMODEL;   KP = DMODEL;     break;
    }
    if (kp >= KP || n >= Npad) return;
    float v0 = 0.f, v1 = 0.f;
    if (n < N) {
        v0 = in[(size_t)(2 * kp) * N + n];
        v1 = in[(size_t)(2 * kp + 1) * N + n];
    }
    out[(size_t)kp * Npad + n] = split2_f16(v0, v1);
}

// ------ 2xFP16 tensor GEMM on pre-split pairs: C = A@B (+bias) ----------------
#define PADU 132

__global__ __launch_bounds__(256, 2)
void tgemm_p(const uint2* __restrict__ A0, const uint2* __restrict__ A1, int lda2,
             const uint2* __restrict__ B0, const uint2* __restrict__ B1, int ldb2,
             float* __restrict__ C0, float* __restrict__ C1,
             uint2* __restrict__ P0, uint2* __restrict__ P1,
             int ldc, int cco0, int cco1,
             int N, int K, int revA_mask, int revC_mask,
             const float* __restrict__ bias)
{
    __shared__ uint2 A2[2][8][PADU];
    __shared__ uint2 B2[2][8][PADU];

    const int z = blockIdx.z;
    const uint2* Ag = z ? A1 : A0;
    const uint2* Bg = z ? B1 : B0;
    float* Cg = z ? C1 : C0;
    uint2* Pg = z ? P1 : P0;
    const int cco = z ? cco1 : cco0;
    const int revA = (revA_mask >> z) & 1;
    const int revC = (revC_mask >> z) & 1;

    const int tid = threadIdx.x;
    const int bn = blockIdx.x * 128;
    const int bm = blockIdx.y * 128;

    const int wid = tid >> 5;
    const int lane = tid & 31;
    const int warp_n = wid & 3;
    const int fg = lane >> 2;
    const int fc = lane & 3;
    const int m_warp = (wid >> 2) * 64;
    const int n_warp = warp_n * 32;

    const int a_row = tid >> 1;
    const int a_kp0 = (tid & 1) * 4;
    int am = bm + a_row;
    if (revA) { int bb = am >> 10; int ll = am & 1023; am = (bb << 10) + (1023 - ll); }
    const uint2* Ap = Ag + (size_t)am * lda2 + a_kp0;

    const int b_kp = tid >> 5;
    const int b_n0 = (tid & 31) * 4;
    const uint2* Bp = Bg + (size_t)b_kp * ldb2 + bn + b_n0;

    float acc[4][4][4];
#pragma unroll
    for (int i = 0; i < 4; i++)
#pragma unroll
        for (int j = 0; j < 4; j++)
#pragma unroll
            for (int r = 0; r < 4; r++) acc[i][j][r] = 0.f;

    const int nk = K / 16;

    // ---- prologue ----
    {
        uint4 a01 = *(const uint4*)(Ap);
        uint4 a23 = *(const uint4*)(Ap + 2);
        A2[0][a_kp0 + 0][a_row] = make_uint2(a01.x, a01.y);
        A2[0][a_kp0 + 1][a_row] = make_uint2(a01.z, a01.w);
        A2[0][a_kp0 + 2][a_row] = make_uint2(a23.x, a23.y);
        A2[0][a_kp0 + 3][a_row] = make_uint2(a23.z, a23.w);
        uint4 b01 = *(const uint4*)(Bp);
        uint4 b23 = *(const uint4*)(Bp + 2);
        *(uint4*)&B2[0][b_kp][b_n0]     = b01;
        *(uint4*)&B2[0][b_kp][b_n0 + 2] = b23;
    }
    __syncthreads();

    for (int it = 0; it < nk; it++) {
        const int buf = it & 1;

        uint4 a01, a23, b01, b23;
        const bool more = (it + 1) < nk;
        if (more) {
            int kp8 = (it + 1) * 8;
            a01 = *(const uint4*)(Ap + kp8);
            a23 = *(const uint4*)(Ap + kp8 + 2);
            b01 = *(const uint4*)(Bp + (size_t)kp8 * ldb2);
            b23 = *(const uint4*)(Bp + (size_t)kp8 * ldb2 + 2);
        }

        {
            u32 bfrag[4][2];
#pragma unroll
            for (int in = 0; in < 4; in++) {
                int n = n_warp + in * 8 + fg;
                bfrag[in][0] = B2[buf][fc][n].x;
                bfrag[in][1] = B2[buf][fc + 4][n].x;
            }
#pragma unroll
            for (int im = 0; im < 4; im++) {
                int m0 = m_warp + im * 16 + fg;
                uint2 a00 = A2[buf][fc][m0];
                uint2 a01r = A2[buf][fc][m0 + 8];
                uint2 a10 = A2[buf][fc + 4][m0];
                uint2 a11 = A2[buf][fc + 4][m0 + 8];
                u32 ah[4] = {a00.x, a01r.x, a10.x, a11.x};
                u32 al[4] = {a00.y, a01r.y, a10.y, a11.y};
#pragma unroll
                for (int in = 0; in < 4; in++) {
                    mma_f16(acc[im][in], ah, bfrag[in]);   // hi*hi
                    mma_f16(acc[im][in], al, bfrag[in]);   // lo*hi
                }
            }
        }

        if (more) {
            const int nb = buf ^ 1;
            A2[nb][a_kp0 + 0][a_row] = make_uint2(a01.x, a01.y);
            A2[nb][a_kp0 + 1][a_row] = make_uint2(a01.z, a01.w);
            A2[nb][a_kp0 + 2][a_row] = make_uint2(a23.x, a23.y);
            A2[nb][a_kp0 + 3][a_row] = make_uint2(a23.z, a23.w);
            *(uint4*)&B2[nb][b_kp][b_n0]     = b01;
            *(uint4*)&B2[nb][b_kp][b_n0 + 2] = b23;
        }
        __syncthreads();
    }

    // ---- epilogue ----
#pragma unroll
    for (int im = 0; im < 4; im++) {
        int mrow0 = bm + m_warp + im * 16 + fg;
        int mrow1 = mrow0 + 8;
        int w0 = mrow0, w1 = mrow1;
        if (revC) {
            int bb = mrow0 >> 10, ll = mrow0 & 1023; w0 = (bb << 10) + (1023 - ll);
            bb = mrow1 >> 10; ll = mrow1 & 1023; w1 = (bb << 10) + (1023 - ll);
        }
        if (Pg) {
            const int ldp = ldc >> 1;
            uint2* P0r = Pg + (size_t)w0 * ldp;
            uint2* P1r = Pg + (size_t)w1 * ldp;
#pragma unroll
            for (int in = 0; in < 4; in++) {
                int n0 = bn + n_warp + in * 8 + fc * 2;
                if (n0 + 1 <= N) {
                    int pc = (cco + n0) >> 1;
                    P0r[pc] = split2_f16(acc[im][in][0], acc[im][in][1]);
                    P1r[pc] = split2_f16(acc[im][in][2], acc[im][in][3]);
                }
            }
        } else {
            float* C0r = Cg + (size_t)w0 * ldc + cco;
            float* C1r = Cg + (size_t)w1 * ldc + cco;
#pragma unroll
            for (int in = 0; in < 4; in++) {
                int n0 = bn + n_warp + in * 8 + fc * 2;
                float b0 = 0.f, b1 = 0.f;
                if (bias) {
                    if (n0 < N) b0 = bias[n0];
                    if (n0 + 1 < N) b1 = bias[n0 + 1];
                }
                if (n0 < N)     { C0r[n0]     = acc[im][in][0] + b0; }
                if (n0 + 1 < N) { C0r[n0 + 1] = acc[im][in][1] + b1; }
                if (n0 < N)     { C1r[n0]     = acc[im][in][2] + b0; }
                if (n0 + 1 < N) { C1r[n0 + 1] = acc[im][in][3] + b1; }
            }
        }
    }
}

// ---------------- conv (causal depthwise, 4 taps) + silu + dt/dA --------------
__global__ __launch_bounds__(256)
void conv_silu_dt(const float* __restrict__ cw0, const float* __restrict__ cb0,
                  const float* __restrict__ dtb0, const float* __restrict__ Al0,
                  const float* __restrict__ cw1, const float* __restrict__ cb1,
                  const float* __restrict__ dtb1, const float* __restrict__ Al1)
{
    const int dir = blockIdx.z;
    const int b = blockIdx.y;
    const int l = blockIdx.x;
    const float* cw  = dir ? cw1  : cw0;
    const float* cb  = dir ? cb1  : cb0;
    const float* dtb = dir ? dtb1 : dtb0;
    const float* Al  = dir ? Al1  : Al0;

    const float* zx = g_zx[dir];
    const int row = b * LSEQ + l;
    float* out = g_xbc[dir] + (size_t)row * CONVCH;

    for (int c = threadIdx.x; c < CONVCH; c += 256) {
        float acc = cb[c];
#pragma unroll
        for (int j = 0; j < 4; j++) {
            int ls = l - 3 + j;
            if (ls >= 0)
                acc = fmaf(cw[j * CONVCH + c],
                           zx[(size_t)(b * LSEQ + ls) * DPROJ + DINNER + c], acc);
        }
        out[c] = acc * (1.f / (1.f + expf(-acc)));
    }

    for (int h = threadIdx.x; h < NHEADS; h += 256) {
        float v = zx[(size_t)row * DPROJ + DINNER + CONVCH + h] + dtb[h];
        float dt = (v > 20.f) ? v : log1pf(expf(v));
        g_dt[dir][row * NHEADS + h] = dt;
        g_dA[dir][row * NHEADS + h] = expf(-expf(Al[h]) * dt);
    }
}

// ---------------- SSD pass 1: 2xFP16 pair-packed (k = s dimension) ------------
// hd[n][p] = sum_s (w_s*B[s,n]) * X[s,p]; pairs packed over adjacent s.
#define PADS 68   // 2*68 % 32 == 8 -> conflict-free LDS.64

__global__ __launch_bounds__(256)
void ssd_state()
{
    const int h = blockIdx.x;
    const int b = blockIdx.y / SSEG;
    const int ch = blockIdx.y % SSEG;
    const int dir = blockIdx.z;
    const int tid = threadIdx.x;
    const int t0 = b * LSEQ + ch * TSEG;
    const float* xbc = g_xbc[dir];

    __shared__ uint2 B2s[32][PADS];   // w*B packed over s: [sp][n]
    __shared__ uint2 X2s[32][PADS];   // X packed over s:   [sp][p]
    __shared__ float das[64], dts_[64], w_[64], ahat_[64];

    if (tid < 64) {
        das[tid]  = g_dA[dir][(size_t)(t0 + tid) * NHEADS + h];
        dts_[tid] = g_dt[dir][(size_t)(t0 + tid) * NHEADS + h];
    }
    __syncthreads();
    if (tid == 0) {
        float acc = 1.f;
        for (int t = 0; t < 64; t++) { acc *= das[t]; ahat_[t] = acc; }
        float suf = 1.f;
        for (int s = 63; s >= 0; s--) { w_[s] = dts_[s] * suf; suf *= das[s]; }
    }
    __syncthreads();
    if (tid < 64)
        g_cump[dir][(size_t)(t0 + tid) * NHEADS + h] = ahat_[tid];

    // stage packed: thread handles sp = tid>>3 (0..31), col4 = (tid&7)*8 .. +7
    {
        int sp = tid >> 3;
        int c0 = (tid & 7) * 8;
        size_t r0 = (size_t)(t0 + 2 * sp) * CONVCH;
        size_t r1 = (size_t)(t0 + 2 * sp + 1) * CONVCH;
        float w0v = w_[2 * sp], w1v = w_[2 * sp + 1];
#pragma unroll
        for (int g = 0; g < 2; g++) {
            int c = c0 + g * 4;
            float4 b0 = *(const float4*)&xbc[r0 + DINNER + c];
            float4 b1 = *(const float4*)&xbc[r1 + DINNER + c];
            B2s[sp][c + 0] = split2_f16(w0v * b0.x, w1v * b1.x);
            B2s[sp][c + 1] = split2_f16(w0v * b0.y, w1v * b1.y);
            B2s[sp][c + 2] = split2_f16(w0v * b0.z, w1v * b1.z);
            B2s[sp][c + 3] = split2_f16(w0v * b0.w, w1v * b1.w);
            float4 x0 = *(const float4*)&xbc[r0 + h * HEADDIM + c];
            float4 x1 = *(const float4*)&xbc[r1 + h * HEADDIM + c];
            X2s[sp][c + 0] = split2_f16(x0.x, x1.x);
            X2s[sp][c + 1] = split2_f16(x0.y, x1.y);
            X2s[sp][c + 2] = split2_f16(x0.z, x1.z);
            X2s[sp][c + 3] = split2_f16(x0.w, x1.w);
        }
    }
    __syncthreads();

    const int wid = tid >> 5, lane = tid & 31, fg = lane >> 2, fc = lane & 3;
    const int m0w = (wid & 3) * 16, n0w = (wid >> 2) * 32;
    float acc[4][4];
#pragma unroll
    for (int i = 0; i < 4; i++)
#pragma unroll
        for (int j = 0; j < 4; j++) acc[i][j] = 0.f;

#pragma unroll
    for (int ks = 0; ks < 4; ks++) {
        const int kp = ks * 8;
        u32 bfrag[4][2];
#pragma unroll
        for (int in = 0; in < 4; in++) {
            int p = n0w + in * 8 + fg;
            bfrag[in][0] = X2s[kp + fc][p].x;
            bfrag[in][1] = X2s[kp + fc + 4][p].x;
        }
        int m0 = m0w + fg;
        uint2 a00 = B2s[kp + fc][m0];
        uint2 a01r = B2s[kp + fc][m0 + 8];
        uint2 a10 = B2s[kp + fc + 4][m0];
        uint2 a11 = B2s[kp + fc + 4][m0 + 8];
        u32 ah[4] = {a00.x, a01r.x, a10.x, a11.x};
        u32 al[4] = {a00.y, a01r.y, a10.y, a11.y};
#pragma unroll
        for (int in = 0; in < 4; in++) {
            mma_f16(acc[in], ah, bfrag[in]);   // hi*hi
            mma_f16(acc[in], al, bfrag[in]);   // lo*hi
        }
        // hi*lo on X: use X lo halves with B hi (keeps X precision too)
        u32 blo[4][2];
#pragma unroll
        for (int in = 0; in < 4; in++) {
            int p = n0w + in * 8 + fg;
            blo[in][0] = X2s[kp + fc][p].y;
            blo[in][1] = X2s[kp + fc + 4][p].y;
        }
#pragma unroll
        for (int in = 0; in < 4; in++)
            mma_f16(acc[in], ah, blo[in]);     // hi*lo
    }

    float* hd = g_hseg + SEGIDX(dir, b, ch, h) * (size_t)(HEADDIM * DSTATE);
#pragma unroll
    for (int in = 0; in < 4; in++) {
        int p = n0w + in * 8 + 2 * fc;
        hd[(m0w + fg) * 64 + p]     = acc[in][0];
        hd[(m0w + fg) * 64 + p + 1] = acc[in][1];
        hd[(m0w + fg + 8) * 64 + p]     = acc[in][2];
        hd[(m0w + fg + 8) * 64 + p + 1] = acc[in][3];
    }
}

// ---------------- SSD pass 2 ----------------
__global__ __launch_bounds__(256)
void ssd_combine()
{
    const int h = blockIdx.x;
    const int b = blockIdx.y;
    const int dir = blockIdx.z;
    const int tid = threadIdx.x;
    const int off = tid * 16;

    float hr[16];
#pragma unroll
    for (int i = 0; i < 16; i++) hr[i] = 0.f;

    for (int seg = 0; seg < SSEG; seg++) {
        size_t base = SEGIDX(dir, b, seg, h) * (size_t)(HEADDIM * DSTATE) + off;
        float* hin = g_hin + base;
#pragma unroll
        for (int i = 0; i < 16; i++) hin[i] = hr[i];
        float aend = g_cump[dir][(size_t)(b * LSEQ + seg * TSEG + TSEG - 1) * NHEADS + h];
        const float* hend = g_hseg + base;
#pragma unroll
        for (int i = 0; i < 16; i++) hr[i] = fmaf(aend, hr[i], hend[i]);
    }
}

// ---------------- warp-level 64x64x64 3xTF32 GEMM helper (ssd_y) --------------
template<int AK, int BK>
__device__ __forceinline__ void wgemm64(float (*acc)[4], const float* As, const float* Bm,
                                        int m0, int n0w, int fg, int fc)
{
#pragma unroll
    for (int k0 = 0; k0 < 64; k0 += 8) {
        u32 bh[4][2], bl[4][2];
#pragma unroll
        for (int in = 0; in < 4; in++) {
            int n = n0w + in * 8 + fg;
            float v0 = BK ? Bm[(k0 + fc) * 72 + n]     : Bm[n * 72 + k0 + fc];
            float v1 = BK ? Bm[(k0 + fc + 4) * 72 + n] : Bm[n * 72 + k0 + fc + 4];
            split_tf32(v0, bh[in][0], bl[in][0]);
            split_tf32(v1, bh[in][1], bl[in][1]);
        }
        float av0 = AK ? As[(k0 + fc) * 72 + m0 + fg]       : As[(m0 + fg) * 72 + k0 + fc];
        float av1 = AK ? As[(k0 + fc) * 72 + m0 + fg + 8]   : As[(m0 + fg + 8) * 72 + k0 + fc];
        float av2 = AK ? As[(k0 + fc + 4) * 72 + m0 + fg]   : As[(m0 + fg) * 72 + k0 + fc + 4];
        float av3 = AK ? As[(k0 + fc + 4) * 72 + m0 + fg + 8] : As[(m0 + fg + 8) * 72 + k0 + fc + 4];
        u32 ah[4], al[4];
        split_tf32(av0, ah[0], al[0]);
        split_tf32(av1, ah[1], al[1]);
        split_tf32(av2, ah[2], al[2]);
        split_tf32(av3, ah[3], al[3]);
#pragma unroll
        for (int in = 0; in < 4; in++) {
            mma_tf32(acc[in], ah, bh[in]);
            mma_tf32(acc[in], al, bh[in]);
            mma_tf32(acc[in], ah, bl[in]);
        }
    }
}

// ---------------- SSD pass 3 ----------------
__global__ __launch_bounds__(256)
void ssd_y(const float* __restrict__ D0, const float* __restrict__ D1)
{
    extern __shared__ float sm[];
    float* Cs  = sm;
    float* Bsm = sm + 4608;
    float* Xs  = sm + 2 * 4608;
    float* Hs  = sm + 3 * 4608;
    float* Ms  = sm + 4 * 4608;
    __shared__ float das[64], dts_[64], ahat_[64];

    const int h = blockIdx.x;
    const int b = blockIdx.y / SSEG;
    const int ch = blockIdx.y % SSEG;
    const int dir = blockIdx.z;
    const int tid = threadIdx.x;
    const int t0 = b * LSEQ + ch * TSEG;
    const float* xbc = g_xbc[dir];
    const float Dh = (dir ? D1 : D0)[h];

    for (int i = tid; i < 1024; i += 256) {
        int r = i >> 4, c4 = (i & 15) * 4;
        size_t row = (size_t)(t0 + r) * CONVCH;
        *(float4*)&Bsm[r * 72 + c4] = *(const float4*)&xbc[row + DINNER + c4];
        *(float4*)&Cs [r * 72 + c4] = *(const float4*)&xbc[row + DINNER + DSTATE + c4];
        *(float4*)&Xs [r * 72 + c4] = *(const float4*)&xbc[row + h * HEADDIM + c4];
    }
    {
        const float* hin = g_hin + SEGIDX(dir, b, ch, h) * (size_t)(HEADDIM * DSTATE);
        for (int i = tid; i < 1024; i += 256) {
            int r = i >> 4, c4 = (i & 15) * 4;
            *(float4*)&Hs[r * 72 + c4] = *(const float4*)&hin[r * 64 + c4];
        }
    }
    if (tid < 64) {
        das[tid]  = g_dA[dir][(size_t)(t0 + tid) * NHEADS + h];
        dts_[tid] = g_dt[dir][(size_t)(t0 + tid) * NHEADS + h];
        ahat_[tid] = g_cump[dir][(size_t)(t0 + tid) * NHEADS + h];
    }
    for (int i = tid; i < 4608; i += 256) Ms[i] = 0.f;
    __syncthreads();

    if (tid < 64) {
        int s = tid;
        float m = dts_[s];
        Ms[s * 72 + s] = m;
        for (int t = s + 1; t < 64; t++) {
            m *= das[t];
            Ms[t * 72 + s] = m;
        }
    }
    __syncthreads();

    const int wid = tid >> 5, lane = tid & 31, fg = lane >> 2, fc = lane & 3;
    const int m0 = (wid & 3) * 16, n0w = (wid >> 2) * 32;

    float accg[4][4];
#pragma unroll
    for (int i = 0; i < 4; i++)
#pragma unroll
        for (int j = 0; j < 4; j++) accg[i][j] = 0.f;
    wgemm64<0, 0>(accg, Cs, Bsm, m0, n0w, fg, fc);
    __syncthreads();

#pragma unroll
    for (int in = 0; in < 4; in++) {
        int s = n0w + in * 8 + 2 * fc;
        int t = m0 + fg;
        Bsm[t * 72 + s]     = accg[in][0] * Ms[t * 72 + s];
        Bsm[t * 72 + s + 1] = accg[in][1] * Ms[t * 72 + s + 1];
        Bsm[(t + 8) * 72 + s]     = accg[in][2] * Ms[(t + 8) * 72 + s];
        Bsm[(t + 8) * 72 + s + 1] = accg[in][3] * Ms[(t + 8) * 72 + s + 1];
    }
    for (int i = tid; i < 4096; i += 256) {
        int t = i >> 6, n = i & 63;
        Cs[t * 72 + n] *= ahat_[t];
    }
    __syncthreads();

    float accy[4][4];
#pragma unroll
    for (int i = 0; i < 4; i++)
#pragma unroll
        for (int j = 0; j < 4; j++) accy[i][j] = 0.f;
    wgemm64<0, 1>(accy, Bsm, Xs, m0, n0w, fg, fc);
    wgemm64<0, 1>(accy, Cs, Hs, m0, n0w, fg, fc);

    float* yout = g_y[dir];
#pragma unroll
    for (int in = 0; in < 4; in++) {
        int p = n0w + in * 8 + 2 * fc;
#pragma unroll
        for (int rr = 0; rr < 2; rr++) {
            int t = m0 + fg + rr * 8;
            float x0 = Xs[t * 72 + p];
            float x1 = Xs[t * 72 + p + 1];
            size_t idx = (size_t)(t0 + t) * DINNER + h * HEADDIM + p;
            yout[idx]     = accy[in][2 * rr + 0] + Dh * x0;
            yout[idx + 1] = accy[in][2 * rr + 1] + Dh * x1;
        }
    }
}

// -------- gated RMSNorm: emits pre-split fp16 pairs directly ------------------
__global__ __launch_bounds__(256)
void gated_norm(const float* __restrict__ nw0, const float* __restrict__ nw1)
{
    const int dir = blockIdx.y;
    const int row = blockIdx.x;
    const float* nw = dir ? nw1 : nw0;
    const float* y = g_y[dir] + (size_t)row * DINNER;
    const float* z = g_zx[dir] + (size_t)row * DPROJ;
    uint2* o = g_gn2[dir] + (size_t)row * (DINNER / 2) + threadIdx.x * 4;

    const int c0 = threadIdx.x * 8;
    float4 y0 = *(const float4*)&y[c0];
    float4 y1 = *(const float4*)&y[c0 + 4];
    float4 z0 = *(const float4*)&z[c0];
    float4 z1 = *(const float4*)&z[c0 + 4];
    float g[8];
    g[0] = y0.x * (z0.x / (1.f + expf(-z0.x)));
    g[1] = y0.y * (z0.y / (1.f + expf(-z0.y)));
    g[2] = y0.z * (z0.z / (1.f + expf(-z0.z)));
    g[3] = y0.w * (z0.w / (1.f + expf(-z0.w)));
    g[4] = y1.x * (z1.x / (1.f + expf(-z1.x)));
    g[5] = y1.y * (z1.y / (1.f + expf(-z1.y)));
    g[6] = y1.z * (z1.z / (1.f + expf(-z1.z)));
    g[7] = y1.w * (z1.w / (1.f + expf(-z1.w)));
    float ss = 0.f;
#pragma unroll
    for (int i = 0; i < 8; i++) ss = fmaf(g[i], g[i], ss);
#pragma unroll
    for (int o2 = 16; o2; o2 >>= 1) ss += __shfl_xor_sync(0xffffffffu, ss, o2);
    __shared__ float red[8];
    if ((threadIdx.x & 31) == 0) red[threadIdx.x >> 5] = ss;
    __syncthreads();
    float tot = red[0] + red[1] + red[2] + red[3] + red[4] + red[5] + red[6] + red[7];
    float scale = rsqrtf(tot * (1.f / DINNER) + 1e-5f);

    float4 w0 = *(const float4*)&nw[c0];
    float4 w1 = *(const float4*)&nw[c0 + 4];
    float v[8];
    v[0] = g[0] * scale * w0.x; v[1] = g[1] * scale * w0.y;
    v[2] = g[2] * scale * w0.z; v[3] = g[3] * scale * w0.w;
    v[4] = g[4] * scale * w1.x; v[5] = g[5] * scale * w1.y;
    v[6] = g[6] * scale * w1.z; v[7] = g[7] * scale * w1.w;
    o[0] = split2_f16(v[0], v[1]);
    o[1] = split2_f16(v[2], v[3]);
    o[2] = split2_f16(v[4], v[5]);
    o[3] = split2_f16(v[6], v[7]);
}

// ---------------- launch ----------------
extern "C" void kernel_launch(void* const* d_in, const int* in_sizes, int n_in,
                              void* d_out, int out_size)
{
    (void)in_sizes; (void)n_in; (void)out_size;
    const float* x      = (const float*)d_in[0];
    const float* fWin   = (const float*)d_in[1];
    const float* fconvw = (const float*)d_in[2];
    const float* fconvb = (const float*)d_in[3];
    const float* fdtb   = (const float*)d_in[4];
    const float* fAlog  = (const float*)d_in[5];
    const float* fD     = (const float*)d_in[6];
    const float* fnormw = (const float*)d_in[7];
    const float* fWout  = (const float*)d_in[8];
    const float* bWin   = (const float*)d_in[9];
    const float* bconvw = (const float*)d_in[10];
    const float* bconvb = (const float*)d_in[11];
    const float* bdtb   = (const float*)d_in[12];
    const float* bAlog  = (const float*)d_in[13];
    const float* bD     = (const float*)d_in[14];
    const float* bnormw = (const float*)d_in[15];
    const float* bWout  = (const float*)d_in[16];
    const float* Wo     = (const float*)d_in[17];
    const float* bo     = (const float*)d_in[18];
    float* out = (float*)d_out;

    static int smem_set = 0;
    if (!smem_set) {
        cudaFuncSetAttribute(ssd_y, cudaFuncAttributeMaxDynamicSharedMemorySize, 5 * 4608 * 4);
        smem_set = 1;
    }

    float* zx;
    uint2 *x2, *fWin2, *bWin2, *fWout2, *bWout2, *Wo2, *gn2, *cat2;
    cudaGetSymbolAddress((void**)&zx, g_zx);
    cudaGetSymbolAddress((void**)&x2, g_x2);
    cudaGetSymbolAddress((void**)&fWin2, g_fWin2);
    cudaGetSymbolAddress((void**)&bWin2, g_bWin2);
    cudaGetSymbolAddress((void**)&fWout2, g_fWout2);
    cudaGetSymbolAddress((void**)&bWout2, g_bWout2);
    cudaGetSymbolAddress((void**)&Wo2, g_Wo2);
    cudaGetSymbolAddress((void**)&gn2, g_gn2);
    cudaGetSymbolAddress((void**)&cat2, g_cat2);
    float* zx0 = zx;
    float* zx1 = zx + (size_t)NTOK * DPROJ;
    uint2* gn2_0 = gn2;
    uint2* gn2_1 = gn2 + (size_t)NTOK * (DINNER / 2);

    // 0) pre-split x and weights to fp16 pairs
    presplitA<<<(NTOK * (DMODEL / 2) / 2 + 255) / 256, 256>>>(x, x2, NTOK * (DMODEL / 2));
    presplitB_all<<<dim3(17, 1024, 5), 256>>>(fWin, bWin, fWout, bWout, Wo,
                                              fWin2, bWin2, fWout2, bWout2, Wo2);

    // 1) input projections (merged dirs; dir1 reads x reversed)
    tgemm_p<<<dim3(NPAD_WIN / 128, NTOK / 128, 2), 256>>>(
        x2, x2, DMODEL / 2, fWin2, bWin2, NPAD_WIN,
        zx0, zx1, nullptr, nullptr, DPROJ, 0, 0,
        DPROJ, DMODEL, /*revA*/0b10, /*revC*/0, nullptr);

    // 2) causal conv + silu + dt/dA
    conv_silu_dt<<<dim3(LSEQ, BSZ, 2), 256>>>(fconvw, fconvb, fdtb, fAlog,
                                              bconvw, bconvb, bdtb, bAlog);

    // 3) SSD tensor-core scan
    ssd_state<<<dim3(NHEADS, BSZ * SSEG, 2), 256>>>();
    ssd_combine<<<dim3(NHEADS, BSZ, 2), 256>>>();
    ssd_y<<<dim3(NHEADS, BSZ * SSEG, 2), 256, 5 * 4608 * 4>>>(fD, bD);

    // 4) gated RMSNorm -> fp16 pairs
    gated_norm<<<dim3(NTOK, 2), 256>>>(fnormw, bnormw);

    // 5) out projections (merged dirs) -> cat2 pairs (dir1 rows flipped back)
    tgemm_p<<<dim3(DMODEL / 128, NTOK / 128, 2), 256>>>(
        gn2_0, gn2_1, DINNER / 2, fWout2, bWout2, DMODEL,
        nullptr, nullptr, cat2, cat2, 2 * DMODEL, 0, DMODEL,
        DMODEL, DINNER, /*revA*/0, /*revC*/0b10, nullptr);

    // 6) final projection + bias
    tgemm_p<<<dim3(DMODEL / 128, NTOK / 128, 1), 256>>>(
        cat2, cat2, DMODEL, Wo2, Wo2, DMODEL,
        out, out, nullptr, nullptr, DMODEL, 0, 0,
        DMODEL, 2 * DMODEL, 0, 0, bo);
}

// round 15
// speedup vs baseline: 1.0040x; 1.0040x over previous
#include <cuda_runtime.h>
#include <cuda_fp16.h>
#include <math.h>

#define BSZ 2
#define LSEQ 1024
#define DMODEL 1024
#define DINNER 2048
#define DSTATE 64
#define NHEADS 32
#define HEADDIM 64
#define CONVCH 2176
#define DPROJ 4256
#define NTOK 2048    // BSZ*LSEQ
#define SSEG 16      // chunks per sequence
#define TSEG 64      // chunk length
#define NPAD_WIN 4352   // 34*128 padded N for input proj weights

typedef unsigned long long u64;
typedef unsigned int u32;

// ---------------- tf32 helpers (ssd kernels) -----------------
__device__ __forceinline__ u32 to_tf32(float v) {
    u32 r; asm("cvt.rna.tf32.f32 %0, %1;" : "=r"(r) : "f"(v)); return r;
}
__device__ __forceinline__ void split_tf32(float v, u32& hi, u32& lo) {
    hi = to_tf32(v);
    lo = to_tf32(v - __uint_as_float(hi));
}
__device__ __forceinline__ void mma_tf32(float* d, const u32* a, const u32* b) {
    asm volatile(
        "mma.sync.aligned.m16n8k8.row.col.f32.tf32.tf32.f32 "
        "{%0,%1,%2,%3}, {%4,%5,%6,%7}, {%8,%9}, {%0,%1,%2,%3};"
        : "+f"(d[0]), "+f"(d[1]), "+f"(d[2]), "+f"(d[3])
        : "r"(a[0]), "r"(a[1]), "r"(a[2]), "r"(a[3]), "r"(b[0]), "r"(b[1]));
}

// ---------------- fp16 helpers -----------------
__device__ __forceinline__ uint2 split2_f16(float v0, float v1) {
    __half h0 = __float2half_rn(v0), h1 = __float2half_rn(v1);
    u32 h = ((u32)__half_as_ushort(h1) << 16) | (u32)__half_as_ushort(h0);
    float r0 = v0 - __half2float(h0);
    float r1 = v1 - __half2float(h1);
    __half l0 = __float2half_rn(r0), l1 = __float2half_rn(r1);
    u32 l = ((u32)__half_as_ushort(l1) << 16) | (u32)__half_as_ushort(l0);
    return make_uint2(h, l);
}
__device__ __forceinline__ void mma_f16(float* d, const u32* a, const u32* b) {
    asm volatile(
        "mma.sync.aligned.m16n8k16.row.col.f32.f16.f16.f32 "
        "{%0,%1,%2,%3}, {%4,%5,%6,%7}, {%8,%9}, {%0,%1,%2,%3};"
        : "+f"(d[0]), "+f"(d[1]), "+f"(d[2]), "+f"(d[3])
        : "r"(a[0]), "r"(a[1]), "r"(a[2]), "r"(a[3]), "r"(b[0]), "r"(b[1]));
}

// ---------------- scratch ----------------
__device__ float g_zx[2][(size_t)NTOK * DPROJ];
__device__ float g_xbc[2][(size_t)NTOK * CONVCH];
__device__ float g_dt[2][NTOK * NHEADS];
__device__ float g_dA[2][NTOK * NHEADS];
__device__ float g_cump[2][NTOK * NHEADS];
__device__ float g_y[2][(size_t)NTOK * DINNER];
#define SEGIDX(dir,b,seg,h) ((((size_t)(dir)*BSZ + (b))*SSEG + (seg))*NHEADS + (h))
__device__ float g_hseg[(size_t)2 * BSZ * SSEG * NHEADS * HEADDIM * DSTATE];
__device__ float g_hin [(size_t)2 * BSZ * SSEG * NHEADS * HEADDIM * DSTATE];

// pre-split fp16 pair buffers (uint2 = {hi-pair, lo-pair} per 2 fp32 elems)
__device__ uint2 g_x2[(size_t)NTOK * (DMODEL / 2)];                // A fmt [m][kp]
__device__ uint2 g_fWin2[(size_t)(DMODEL / 2) * NPAD_WIN];         // B fmt [kp][n]
__device__ uint2 g_bWin2[(size_t)(DMODEL / 2) * NPAD_WIN];
__device__ uint2 g_fWout2[(size_t)(DINNER / 2) * DMODEL];
__device__ uint2 g_bWout2[(size_t)(DINNER / 2) * DMODEL];
__device__ uint2 g_Wo2[(size_t)DMODEL * DMODEL];
__device__ uint2 g_gn2[2][(size_t)NTOK * (DINNER / 2)];            // A fmt
__device__ uint2 g_cat2[(size_t)NTOK * DMODEL];                    // A fmt

// ---------------- pre-split kernels ----------------
__global__ __launch_bounds__(256)
void presplitA(const float* __restrict__ in, uint2* __restrict__ out, int total)
{
    int t = (blockIdx.x * 256 + threadIdx.x) * 2;
    if (t >= total) return;
    float4 v = *(const float4*)(in + (size_t)t * 2);
    out[t]     = split2_f16(v.x, v.y);
    out[t + 1] = split2_f16(v.z, v.w);
}
__global__ __launch_bounds__(256)
void presplitB_all(const float* __restrict__ fWin, const float* __restrict__ bWin,
                   const float* __restrict__ fWout, const float* __restrict__ bWout,
                   const float* __restrict__ Wo,
                   uint2* __restrict__ o0, uint2* __restrict__ o1,
                   uint2* __restrict__ o2, uint2* __restrict__ o3,
                   uint2* __restrict__ o4)
{
    const int job = blockIdx.z;
    const int kp = blockIdx.y;
    const int n = blockIdx.x * 256 + threadIdx.x;
    const float* in; uint2* out; int N, Npad, KP;
    switch (job) {
        case 0: in = fWin;  out = o0; N = DPROJ;  Npad = NPAD_WIN; KP = DMODEL / 2; break;
        case 1: in = bWin;  out = o1; N = DPROJ;  Npad = NPAD_WIN; KP = DMODEL / 2; break;
        case 2: in = fWout; out = o2; N = DMODEL; Npad = DMODEL;   KP = DINNER / 2; break;
        case 3: in = bWout; out = o3; N = DMODEL; Npad = DMODEL;   KP = DINNER / 2; break;
        default: in = Wo;   out = o4; N = DMODEL; Npad = DMODEL;   KP = DMODEL;     break;
    }
    if (kp >= KP || n >= Npad) return;
    float v0 = 0.f, v1 = 0.f;
    if (n < N) {
        v0 = in[(size_t)(2 * kp) * N + n];
        v1 = in[(size_t)(2 * kp + 1) * N + n];
    }
    out[(size_t)kp * Npad + n] = split2_f16(v0, v1);
}

// ------ 2xFP16 tensor GEMM on pre-split pairs: C = A@B (+bias) ----------------
#define PADU 132

__global__ __launch_bounds__(256, 2)
void tgemm_p(const uint2* __restrict__ A0, const uint2* __restrict__ A1, int lda2,
             const uint2* __restrict__ B0, const uint2* __restrict__ B1, int ldb2,
             float* __restrict__ C0, float* __restrict__ C1,
             uint2* __restrict__ P0, uint2* __restrict__ P1,
             int ldc, int cco0, int cco1,
             int N, int K, int revA_mask, int revC_mask,
             const float* __restrict__ bias)
{
    __shared__ uint2 A2[2][8][PADU];
    __shared__ uint2 B2[2][8][PADU];

    const int z = blockIdx.z;
    const uint2* Ag = z ? A1 : A0;
    const uint2* Bg = z ? B1 : B0;
    float* Cg = z ? C1 : C0;
    uint2* Pg = z ? P1 : P0;
    const int cco = z ? cco1 : cco0;
    const int revA = (revA_mask >> z) & 1;
    const int revC = (revC_mask >> z) & 1;

    const int tid = threadIdx.x;
    const int bn = blockIdx.x * 128;
    const int bm = blockIdx.y * 128;

    const int wid = tid >> 5;
    const int lane = tid & 31;
    const int warp_n = wid & 3;
    const int fg = lane >> 2;
    const int fc = lane & 3;
    const int m_warp = (wid >> 2) * 64;
    const int n_warp = warp_n * 32;

    const int a_row = tid >> 1;
    const int a_kp0 = (tid & 1) * 4;
    int am = bm + a_row;
    if (revA) { int bb = am >> 10; int ll = am & 1023; am = (bb << 10) + (1023 - ll); }
    const uint2* Ap = Ag + (size_t)am * lda2 + a_kp0;

    const int b_kp = tid >> 5;
    const int b_n0 = (tid & 31) * 4;
    const uint2* Bp = Bg + (size_t)b_kp * ldb2 + bn + b_n0;

    float acc[4][4][4];
#pragma unroll
    for (int i = 0; i < 4; i++)
#pragma unroll
        for (int j = 0; j < 4; j++)
#pragma unroll
            for (int r = 0; r < 4; r++) acc[i][j][r] = 0.f;

    const int nk = K / 16;

    // ---- prologue ----
    {
        uint4 a01 = *(const uint4*)(Ap);
        uint4 a23 = *(const uint4*)(Ap + 2);
        A2[0][a_kp0 + 0][a_row] = make_uint2(a01.x, a01.y);
        A2[0][a_kp0 + 1][a_row] = make_uint2(a01.z, a01.w);
        A2[0][a_kp0 + 2][a_row] = make_uint2(a23.x, a23.y);
        A2[0][a_kp0 + 3][a_row] = make_uint2(a23.z, a23.w);
        uint4 b01 = *(const uint4*)(Bp);
        uint4 b23 = *(const uint4*)(Bp + 2);
        *(uint4*)&B2[0][b_kp][b_n0]     = b01;
        *(uint4*)&B2[0][b_kp][b_n0 + 2] = b23;
    }
    __syncthreads();

    for (int it = 0; it < nk; it++) {
        const int buf = it & 1;

        uint4 a01, a23, b01, b23;
        const bool more = (it + 1) < nk;
        if (more) {
            int kp8 = (it + 1) * 8;
            a01 = *(const uint4*)(Ap + kp8);
            a23 = *(const uint4*)(Ap + kp8 + 2);
            b01 = *(const uint4*)(Bp + (size_t)kp8 * ldb2);
            b23 = *(const uint4*)(Bp + (size_t)kp8 * ldb2 + 2);
        }

        {
            u32 bfrag[4][2];
#pragma unroll
            for (int in = 0; in < 4; in++) {
                int n = n_warp + in * 8 + fg;
                bfrag[in][0] = B2[buf][fc][n].x;
                bfrag[in][1] = B2[buf][fc + 4][n].x;
            }
#pragma unroll
            for (int im = 0; im < 4; im++) {
                int m0 = m_warp + im * 16 + fg;
                uint2 a00 = A2[buf][fc][m0];
                uint2 a01r = A2[buf][fc][m0 + 8];
                uint2 a10 = A2[buf][fc + 4][m0];
                uint2 a11 = A2[buf][fc + 4][m0 + 8];
                u32 ah[4] = {a00.x, a01r.x, a10.x, a11.x};
                u32 al[4] = {a00.y, a01r.y, a10.y, a11.y};
#pragma unroll
                for (int in = 0; in < 4; in++) {
                    mma_f16(acc[im][in], ah, bfrag[in]);   // hi*hi
                    mma_f16(acc[im][in], al, bfrag[in]);   // lo*hi
                }
            }
        }

        if (more) {
            const int nb = buf ^ 1;
            A2[nb][a_kp0 + 0][a_row] = make_uint2(a01.x, a01.y);
            A2[nb][a_kp0 + 1][a_row] = make_uint2(a01.z, a01.w);
            A2[nb][a_kp0 + 2][a_row] = make_uint2(a23.x, a23.y);
            A2[nb][a_kp0 + 3][a_row] = make_uint2(a23.z, a23.w);
            *(uint4*)&B2[nb][b_kp][b_n0]     = b01;
            *(uint4*)&B2[nb][b_kp][b_n0 + 2] = b23;
        }
        __syncthreads();
    }

    // ---- epilogue ----
#pragma unroll
    for (int im = 0; im < 4; im++) {
        int mrow0 = bm + m_warp + im * 16 + fg;
        int mrow1 = mrow0 + 8;
        int w0 = mrow0, w1 = mrow1;
        if (revC) {
            int bb = mrow0 >> 10, ll = mrow0 & 1023; w0 = (bb << 10) + (1023 - ll);
            bb = mrow1 >> 10; ll = mrow1 & 1023; w1 = (bb << 10) + (1023 - ll);
        }
        if (Pg) {
            const int ldp = ldc >> 1;
            uint2* P0r = Pg + (size_t)w0 * ldp;
            uint2* P1r = Pg + (size_t)w1 * ldp;
#pragma unroll
            for (int in = 0; in < 4; in++) {
                int n0 = bn + n_warp + in * 8 + fc * 2;
                if (n0 + 1 <= N) {
                    int pc = (cco + n0) >> 1;
                    P0r[pc] = split2_f16(acc[im][in][0], acc[im][in][1]);
                    P1r[pc] = split2_f16(acc[im][in][2], acc[im][in][3]);
                }
            }
        } else {
            float* C0r = Cg + (size_t)w0 * ldc + cco;
            float* C1r = Cg + (size_t)w1 * ldc + cco;
#pragma unroll
            for (int in = 0; in < 4; in++) {
                int n0 = bn + n_warp + in * 8 + fc * 2;
                float b0 = 0.f, b1 = 0.f;
                if (bias) {
                    if (n0 < N) b0 = bias[n0];
                    if (n0 + 1 < N) b1 = bias[n0 + 1];
                }
                if (n0 < N)     { C0r[n0]     = acc[im][in][0] + b0; }
                if (n0 + 1 < N) { C0r[n0 + 1] = acc[im][in][1] + b1; }
                if (n0 < N)     { C1r[n0]     = acc[im][in][2] + b0; }
                if (n0 + 1 < N) { C1r[n0 + 1] = acc[im][in][3] + b1; }
            }
        }
    }
}

// ---------------- conv (causal depthwise, 4 taps) + silu + dt/dA --------------
// float4 vectorized over channels (CONVCH = 2176 = 544 float4)
__global__ __launch_bounds__(256)
void conv_silu_dt(const float* __restrict__ cw0, const float* __restrict__ cb0,
                  const float* __restrict__ dtb0, const float* __restrict__ Al0,
                  const float* __restrict__ cw1, const float* __restrict__ cb1,
                  const float* __restrict__ dtb1, const float* __restrict__ Al1)
{
    const int dir = blockIdx.z;
    const int b = blockIdx.y;
    const int l = blockIdx.x;
    const float* cw  = dir ? cw1  : cw0;
    const float* cb  = dir ? cb1  : cb0;
    const float* dtb = dir ? dtb1 : dtb0;
    const float* Al  = dir ? Al1  : Al0;

    const float* zx = g_zx[dir];
    const int row = b * LSEQ + l;
    float* out = g_xbc[dir] + (size_t)row * CONVCH;

    for (int c4 = threadIdx.x; c4 < CONVCH / 4; c4 += 256) {
        const int c = c4 * 4;
        float4 acc = *(const float4*)&cb[c];
#pragma unroll
        for (int j = 0; j < 4; j++) {
            int ls = l - 3 + j;
            if (ls >= 0) {
                float4 w = *(const float4*)&cw[j * CONVCH + c];
                float4 v = *(const float4*)&zx[(size_t)(b * LSEQ + ls) * DPROJ + DINNER + c];
                acc.x = fmaf(w.x, v.x, acc.x);
                acc.y = fmaf(w.y, v.y, acc.y);
                acc.z = fmaf(w.z, v.z, acc.z);
                acc.w = fmaf(w.w, v.w, acc.w);
            }
        }
        float4 o;
        o.x = acc.x * (1.f / (1.f + expf(-acc.x)));
        o.y = acc.y * (1.f / (1.f + expf(-acc.y)));
        o.z = acc.z * (1.f / (1.f + expf(-acc.z)));
        o.w = acc.w * (1.f / (1.f + expf(-acc.w)));
        *(float4*)&out[c] = o;
    }

    for (int h = threadIdx.x; h < NHEADS; h += 256) {
        float v = zx[(size_t)row * DPROJ + DINNER + CONVCH + h] + dtb[h];
        float dt = (v > 20.f) ? v : log1pf(expf(v));
        g_dt[dir][row * NHEADS + h] = dt;
        g_dA[dir][row * NHEADS + h] = expf(-expf(Al[h]) * dt);
    }
}

// ---------------- warp-level 64x64x64 3xTF32 GEMM helper (ssd) ----------------
template<int AK, int BK>
__device__ __forceinline__ void wgemm64(float (*acc)[4], const float* As, const float* Bm,
                                        int m0, int n0w, int fg, int fc)
{
#pragma unroll
    for (int k0 = 0; k0 < 64; k0 += 8) {
        u32 bh[4][2], bl[4][2];
#pragma unroll
        for (int in = 0; in < 4; in++) {
            int n = n0w + in * 8 + fg;
            float v0 = BK ? Bm[(k0 + fc) * 72 + n]     : Bm[n * 72 + k0 + fc];
            float v1 = BK ? Bm[(k0 + fc + 4) * 72 + n] : Bm[n * 72 + k0 + fc + 4];
            split_tf32(v0, bh[in][0], bl[in][0]);
            split_tf32(v1, bh[in][1], bl[in][1]);
        }
        float av0 = AK ? As[(k0 + fc) * 72 + m0 + fg]       : As[(m0 + fg) * 72 + k0 + fc];
        float av1 = AK ? As[(k0 + fc) * 72 + m0 + fg + 8]   : As[(m0 + fg + 8) * 72 + k0 + fc];
        float av2 = AK ? As[(k0 + fc + 4) * 72 + m0 + fg]   : As[(m0 + fg) * 72 + k0 + fc + 4];
        float av3 = AK ? As[(k0 + fc + 4) * 72 + m0 + fg + 8] : As[(m0 + fg + 8) * 72 + k0 + fc + 4];
        u32 ah[4], al[4];
        split_tf32(av0, ah[0], al[0]);
        split_tf32(av1, ah[1], al[1]);
        split_tf32(av2, ah[2], al[2]);
        split_tf32(av3, ah[3], al[3]);
#pragma unroll
        for (int in = 0; in < 4; in++) {
            mma_tf32(acc[in], ah, bh[in]);
            mma_tf32(acc[in], al, bh[in]);
            mma_tf32(acc[in], ah, bl[in]);
        }
    }
}

// ---------------- SSD pass 1 (3xTF32, proven R13 version) ----------------
__global__ __launch_bounds__(256)
void ssd_state()
{
    const int h = blockIdx.x;
    const int b = blockIdx.y / SSEG;
    const int ch = blockIdx.y % SSEG;
    const int dir = blockIdx.z;
    const int tid = threadIdx.x;
    const int t0 = b * LSEQ + ch * TSEG;
    const float* xbc = g_xbc[dir];

    __shared__ float Bs[64 * 72];
    __shared__ float Xs[64 * 72];
    __shared__ float das[64], dts_[64], w_[64], ahat_[64];

    for (int i = tid; i < 1024; i += 256) {
        int r = i >> 4, c4 = (i & 15) * 4;
        size_t row = (size_t)(t0 + r) * CONVCH;
        *(float4*)&Bs[r * 72 + c4] = *(const float4*)&xbc[row + DINNER + c4];
        *(float4*)&Xs[r * 72 + c4] = *(const float4*)&xbc[row + h * HEADDIM + c4];
    }
    if (tid < 64) {
        das[tid]  = g_dA[dir][(size_t)(t0 + tid) * NHEADS + h];
        dts_[tid] = g_dt[dir][(size_t)(t0 + tid) * NHEADS + h];
    }
    __syncthreads();
    if (tid == 0) {
        float acc = 1.f;
        for (int t = 0; t < 64; t++) { acc *= das[t]; ahat_[t] = acc; }
        float suf = 1.f;
        for (int s = 63; s >= 0; s--) { w_[s] = dts_[s] * suf; suf *= das[s]; }
    }
    __syncthreads();
    if (tid < 64)
        g_cump[dir][(size_t)(t0 + tid) * NHEADS + h] = ahat_[tid];
    for (int i = tid; i < 4096; i += 256) {
        int s = i >> 6, n = i & 63;
        Bs[s * 72 + n] *= w_[s];
    }
    __syncthreads();

    const int wid = tid >> 5, lane = tid & 31, fg = lane >> 2, fc = lane & 3;
    const int m0 = (wid & 3) * 16, n0w = (wid >> 2) * 32;
    float acc[4][4];
#pragma unroll
    for (int i = 0; i < 4; i++)
#pragma unroll
        for (int j = 0; j < 4; j++) acc[i][j] = 0.f;
    wgemm64<1, 1>(acc, Bs, Xs, m0, n0w, fg, fc);

    float* hd = g_hseg + SEGIDX(dir, b, ch, h) * (size_t)(HEADDIM * DSTATE);
#pragma unroll
    for (int in = 0; in < 4; in++) {
        int p = n0w + in * 8 + 2 * fc;
        hd[(m0 + fg) * 64 + p]     = acc[in][0];
        hd[(m0 + fg) * 64 + p + 1] = acc[in][1];
        hd[(m0 + fg + 8) * 64 + p]     = acc[in][2];
        hd[(m0 + fg + 8) * 64 + p + 1] = acc[in][3];
    }
}

// ---------------- SSD pass 2 ----------------
__global__ __launch_bounds__(256)
void ssd_combine()
{
    const int h = blockIdx.x;
    const int b = blockIdx.y;
    const int dir = blockIdx.z;
    const int tid = threadIdx.x;
    const int off = tid * 16;

    float hr[16];
#pragma unroll
    for (int i = 0; i < 16; i++) hr[i] = 0.f;

    for (int seg = 0; seg < SSEG; seg++) {
        size_t base = SEGIDX(dir, b, seg, h) * (size_t)(HEADDIM * DSTATE) + off;
        float* hin = g_hin + base;
#pragma unroll
        for (int i = 0; i < 16; i++) hin[i] = hr[i];
        float aend = g_cump[dir][(size_t)(b * LSEQ + seg * TSEG + TSEG - 1) * NHEADS + h];
        const float* hend = g_hseg + base;
#pragma unroll
        for (int i = 0; i < 16; i++) hr[i] = fmaf(aend, hr[i], hend[i]);
    }
}

// ---------------- SSD pass 3 ----------------
__global__ __launch_bounds__(256)
void ssd_y(const float* __restrict__ D0, const float* __restrict__ D1)
{
    extern __shared__ float sm[];
    float* Cs  = sm;
    float* Bsm = sm + 4608;
    float* Xs  = sm + 2 * 4608;
    float* Hs  = sm + 3 * 4608;
    float* Ms  = sm + 4 * 4608;
    __shared__ float das[64], dts_[64], ahat_[64];

    const int h = blockIdx.x;
    const int b = blockIdx.y / SSEG;
    const int ch = blockIdx.y % SSEG;
    const int dir = blockIdx.z;
    const int tid = threadIdx.x;
    const int t0 = b * LSEQ + ch * TSEG;
    const float* xbc = g_xbc[dir];
    const float Dh = (dir ? D1 : D0)[h];

    for (int i = tid; i < 1024; i += 256) {
        int r = i >> 4, c4 = (i & 15) * 4;
        size_t row = (size_t)(t0 + r) * CONVCH;
        *(float4*)&Bsm[r * 72 + c4] = *(const float4*)&xbc[row + DINNER + c4];
        *(float4*)&Cs [r * 72 + c4] = *(const float4*)&xbc[row + DINNER + DSTATE + c4];
        *(float4*)&Xs [r * 72 + c4] = *(const float4*)&xbc[row + h * HEADDIM + c4];
    }
    {
        const float* hin = g_hin + SEGIDX(dir, b, ch, h) * (size_t)(HEADDIM * DSTATE);
        for (int i = tid; i < 1024; i += 256) {
            int r = i >> 4, c4 = (i & 15) * 4;
            *(float4*)&Hs[r * 72 + c4] = *(const float4*)&hin[r * 64 + c4];
        }
    }
    if (tid < 64) {
        das[tid]  = g_dA[dir][(size_t)(t0 + tid) * NHEADS + h];
        dts_[tid] = g_dt[dir][(size_t)(t0 + tid) * NHEADS + h];
        ahat_[tid] = g_cump[dir][(size_t)(t0 + tid) * NHEADS + h];
    }
    for (int i = tid; i < 4608; i += 256) Ms[i] = 0.f;
    __syncthreads();

    if (tid < 64) {
        int s = tid;
        float m = dts_[s];
        Ms[s * 72 + s] = m;
        for (int t = s + 1; t < 64; t++) {
            m *= das[t];
            Ms[t * 72 + s] = m;
        }
    }
    __syncthreads();

    const int wid = tid >> 5, lane = tid & 31, fg = lane >> 2, fc = lane & 3;
    const int m0 = (wid & 3) * 16, n0w = (wid >> 2) * 32;

    float accg[4][4];
#pragma unroll
    for (int i = 0; i < 4; i++)
#pragma unroll
        for (int j = 0; j < 4; j++) accg[i][j] = 0.f;
    wgemm64<0, 0>(accg, Cs, Bsm, m0, n0w, fg, fc);
    __syncthreads();

#pragma unroll
    for (int in = 0; in < 4; in++) {
        int s = n0w + in * 8 + 2 * fc;
        int t = m0 + fg;
        Bsm[t * 72 + s]     = accg[in][0] * Ms[t * 72 + s];
        Bsm[t * 72 + s + 1] = accg[in][1] * Ms[t * 72 + s + 1];
        Bsm[(t + 8) * 72 + s]     = accg[in][2] * Ms[(t + 8) * 72 + s];
        Bsm[(t + 8) * 72 + s + 1] = accg[in][3] * Ms[(t + 8) * 72 + s + 1];
    }
    for (int i = tid; i < 4096; i += 256) {
        int t = i >> 6, n = i & 63;
        Cs[t * 72 + n] *= ahat_[t];
    }
    __syncthreads();

    float accy[4][4];
#pragma unroll
    for (int i = 0; i < 4; i++)
#pragma unroll
        for (int j = 0; j < 4; j++) accy[i][j] = 0.f;
    wgemm64<0, 1>(accy, Bsm, Xs, m0, n0w, fg, fc);
    wgemm64<0, 1>(accy, Cs, Hs, m0, n0w, fg, fc);

    float* yout = g_y[dir];
#pragma unroll
    for (int in = 0; in < 4; in++) {
        int p = n0w + in * 8 + 2 * fc;
#pragma unroll
        for (int rr = 0; rr < 2; rr++) {
            int t = m0 + fg + rr * 8;
            float x0 = Xs[t * 72 + p];
            float x1 = Xs[t * 72 + p + 1];
            size_t idx = (size_t)(t0 + t) * DINNER + h * HEADDIM + p;
            yout[idx]     = accy[in][2 * rr + 0] + Dh * x0;
            yout[idx + 1] = accy[in][2 * rr + 1] + Dh * x1;
        }
    }
}

// -------- gated RMSNorm: emits pre-split fp16 pairs directly ------------------
__global__ __launch_bounds__(256)
void gated_norm(const float* __restrict__ nw0, const float* __restrict__ nw1)
{
    const int dir = blockIdx.y;
    const int row = blockIdx.x;
    const float* nw = dir ? nw1 : nw0;
    const float* y = g_y[dir] + (size_t)row * DINNER;
    const float* z = g_zx[dir] + (size_t)row * DPROJ;
    uint2* o = g_gn2[dir] + (size_t)row * (DINNER / 2) + threadIdx.x * 4;

    const int c0 = threadIdx.x * 8;
    float4 y0 = *(const float4*)&y[c0];
    float4 y1 = *(const float4*)&y[c0 + 4];
    float4 z0 = *(const float4*)&z[c0];
    float4 z1 = *(const float4*)&z[c0 + 4];
    float g[8];
    g[0] = y0.x * (z0.x / (1.f + expf(-z0.x)));
    g[1] = y0.y * (z0.y / (1.f + expf(-z0.y)));
    g[2] = y0.z * (z0.z / (1.f + expf(-z0.z)));
    g[3] = y0.w * (z0.w / (1.f + expf(-z0.w)));
    g[4] = y1.x * (z1.x / (1.f + expf(-z1.x)));
    g[5] = y1.y * (z1.y / (1.f + expf(-z1.y)));
    g[6] = y1.z * (z1.z / (1.f + expf(-z1.z)));
    g[7] = y1.w * (z1.w / (1.f + expf(-z1.w)));
    float ss = 0.f;
#pragma unroll
    for (int i = 0; i < 8; i++) ss = fmaf(g[i], g[i], ss);
#pragma unroll
    for (int o2 = 16; o2; o2 >>= 1) ss += __shfl_xor_sync(0xffffffffu, ss, o2);
    __shared__ float red[8];
    if ((threadIdx.x & 31) == 0) red[threadIdx.x >> 5] = ss;
    __syncthreads();
    float tot = red[0] + red[1] + red[2] + red[3] + red[4] + red[5] + red[6] + red[7];
    float scale = rsqrtf(tot * (1.f / DINNER) + 1e-5f);

    float4 w0 = *(const float4*)&nw[c0];
    float4 w1 = *(const float4*)&nw[c0 + 4];
    float v[8];
    v[0] = g[0] * scale * w0.x; v[1] = g[1] * scale * w0.y;
    v[2] = g[2] * scale * w0.z; v[3] = g[3] * scale * w0.w;
    v[4] = g[4] * scale * w1.x; v[5] = g[5] * scale * w1.y;
    v[6] = g[6] * scale * w1.z; v[7] = g[7] * scale * w1.w;
    o[0] = split2_f16(v[0], v[1]);
    o[1] = split2_f16(v[2], v[3]);
    o[2] = split2_f16(v[4], v[5]);
    o[3] = split2_f16(v[6], v[7]);
}

// ---------------- launch ----------------
extern "C" void kernel_launch(void* const* d_in, const int* in_sizes, int n_in,
                              void* d_out, int out_size)
{
    (void)in_sizes; (void)n_in; (void)out_size;
    const float* x      = (const float*)d_in[0];
    const float* fWin   = (const float*)d_in[1];
    const float* fconvw = (const float*)d_in[2];
    const float* fconvb = (const float*)d_in[3];
    const float* fdtb   = (const float*)d_in[4];
    const float* fAlog  = (const float*)d_in[5];
    const float* fD     = (const float*)d_in[6];
    const float* fnormw = (const float*)d_in[7];
    const float* fWout  = (const float*)d_in[8];
    const float* bWin   = (const float*)d_in[9];
    const float* bconvw = (const float*)d_in[10];
    const float* bconvb = (const float*)d_in[11];
    const float* bdtb   = (const float*)d_in[12];
    const float* bAlog  = (const float*)d_in[13];
    const float* bD     = (const float*)d_in[14];
    const float* bnormw = (const float*)d_in[15];
    const float* bWout  = (const float*)d_in[16];
    const float* Wo     = (const float*)d_in[17];
    const float* bo     = (const float*)d_in[18];
    float* out = (float*)d_out;

    static int smem_set = 0;
    if (!smem_set) {
        cudaFuncSetAttribute(ssd_y, cudaFuncAttributeMaxDynamicSharedMemorySize, 5 * 4608 * 4);
        smem_set = 1;
    }

    float* zx;
    uint2 *x2, *fWin2, *bWin2, *fWout2, *bWout2, *Wo2, *gn2, *cat2;
    cudaGetSymbolAddress((void**)&zx, g_zx);
    cudaGetSymbolAddress((void**)&x2, g_x2);
    cudaGetSymbolAddress((void**)&fWin2, g_fWin2);
    cudaGetSymbolAddress((void**)&bWin2, g_bWin2);
    cudaGetSymbolAddress((void**)&fWout2, g_fWout2);
    cudaGetSymbolAddress((void**)&bWout2, g_bWout2);
    cudaGetSymbolAddress((void**)&Wo2, g_Wo2);
    cudaGetSymbolAddress((void**)&gn2, g_gn2);
    cudaGetSymbolAddress((void**)&cat2, g_cat2);
    float* zx0 = zx;
    float* zx1 = zx + (size_t)NTOK * DPROJ;
    uint2* gn2_0 = gn2;
    uint2* gn2_1 = gn2 + (size_t)NTOK * (DINNER / 2);

    // 0) pre-split x and weights to fp16 pairs
    presplitA<<<(NTOK * (DMODEL / 2) / 2 + 255) / 256, 256>>>(x, x2, NTOK * (DMODEL / 2));
    presplitB_all<<<dim3(17, 1024, 5), 256>>>(fWin, bWin, fWout, bWout, Wo,
                                              fWin2, bWin2, fWout2, bWout2, Wo2);

    // 1) input projections (merged dirs; dir1 reads x reversed)
    tgemm_p<<<dim3(NPAD_WIN / 128, NTOK / 128, 2), 256>>>(
        x2, x2, DMODEL / 2, fWin2, bWin2, NPAD_WIN,
        zx0, zx1, nullptr, nullptr, DPROJ, 0, 0,
        DPROJ, DMODEL, /*revA*/0b10, /*revC*/0, nullptr);

    // 2) causal conv + silu + dt/dA
    conv_silu_dt<<<dim3(LSEQ, BSZ, 2), 256>>>(fconvw, fconvb, fdtb, fAlog,
                                              bconvw, bconvb, bdtb, bAlog);

    // 3) SSD tensor-core scan
    ssd_state<<<dim3(NHEADS, BSZ * SSEG, 2), 256>>>();
    ssd_combine<<<dim3(NHEADS, BSZ, 2), 256>>>();
    ssd_y<<<dim3(NHEADS, BSZ * SSEG, 2), 256, 5 * 4608 * 4>>>(fD, bD);

    // 4) gated RMSNorm -> fp16 pairs
    gated_norm<<<dim3(NTOK, 2), 256>>>(fnormw, bnormw);

    // 5) out projections (merged dirs) -> cat2 pairs (dir1 rows flipped back)
    tgemm_p<<<dim3(DMODEL / 128, NTOK / 128, 2), 256>>>(
        gn2_0, gn2_1, DINNER / 2, fWout2, bWout2, DMODEL,
        nullptr, nullptr, cat2, cat2, 2 * DMODEL, 0, DMODEL,
        DMODEL, DINNER, /*revA*/0, /*revC*/0b10, nullptr);

    // 6) final projection + bias
    tgemm_p<<<dim3(DMODEL / 128, NTOK / 128, 1), 256>>>(
        cat2, cat2, DMODEL, Wo2, Wo2, DMODEL,
        out, out, nullptr, nullptr, DMODEL, 0, 0,
        DMODEL, 2 * DMODEL, 0, 0, bo);
}

// round 16
// speedup vs baseline: 1.0277x; 1.0236x over previous
#include <cuda_runtime.h>
#include <cuda_fp16.h>
#include <math.h>

#define BSZ 2
#define LSEQ 1024
#define DMODEL 1024
#define DINNER 2048
#define DSTATE 64
#define NHEADS 32
#define HEADDIM 64
#define CONVCH 2176
#define DPROJ 4256
#define NTOK 2048    // BSZ*LSEQ
#define SSEG 16      // chunks per sequence
#define TSEG 64      // chunk length
#define NPAD_WIN 4352   // 34*128 padded N for input proj weights

typedef unsigned long long u64;
typedef unsigned int u32;

// ---------------- tf32 helpers (ssd kernels) -----------------
__device__ __forceinline__ u32 to_tf32(float v) {
    u32 r; asm("cvt.rna.tf32.f32 %0, %1;" : "=r"(r) : "f"(v)); return r;
}
__device__ __forceinline__ void split_tf32(float v, u32& hi, u32& lo) {
    hi = to_tf32(v);
    lo = to_tf32(v - __uint_as_float(hi));
}
__device__ __forceinline__ void mma_tf32(float* d, const u32* a, const u32* b) {
    asm volatile(
        "mma.sync.aligned.m16n8k8.row.col.f32.tf32.tf32.f32 "
        "{%0,%1,%2,%3}, {%4,%5,%6,%7}, {%8,%9}, {%0,%1,%2,%3};"
        : "+f"(d[0]), "+f"(d[1]), "+f"(d[2]), "+f"(d[3])
        : "r"(a[0]), "r"(a[1]), "r"(a[2]), "r"(a[3]), "r"(b[0]), "r"(b[1]));
}

// ---------------- fp16 helpers -----------------
__device__ __forceinline__ uint2 split2_f16(float v0, float v1) {
    __half h0 = __float2half_rn(v0), h1 = __float2half_rn(v1);
    u32 h = ((u32)__half_as_ushort(h1) << 16) | (u32)__half_as_ushort(h0);
    float r0 = v0 - __half2float(h0);
    float r1 = v1 - __half2float(h1);
    __half l0 = __float2half_rn(r0), l1 = __float2half_rn(r1);
    u32 l = ((u32)__half_as_ushort(l1) << 16) | (u32)__half_as_ushort(l0);
    return make_uint2(h, l);
}
__device__ __forceinline__ void mma_f16(float* d, const u32* a, const u32* b) {
    asm volatile(
        "mma.sync.aligned.m16n8k16.row.col.f32.f16.f16.f32 "
        "{%0,%1,%2,%3}, {%4,%5,%6,%7}, {%8,%9}, {%0,%1,%2,%3};"
        : "+f"(d[0]), "+f"(d[1]), "+f"(d[2]), "+f"(d[3])
        : "r"(a[0]), "r"(a[1]), "r"(a[2]), "r"(a[3]), "r"(b[0]), "r"(b[1]));
}

// ---------------- scratch ----------------
__device__ float g_zx[2][(size_t)NTOK * DPROJ];
__device__ float g_xbc[2][(size_t)NTOK * CONVCH];
__device__ float g_dt[2][NTOK * NHEADS];
__device__ float g_dA[2][NTOK * NHEADS];
__device__ float g_cump[2][NTOK * NHEADS];
__device__ float g_y[2][(size_t)NTOK * DINNER];
#define SEGIDX(dir,b,seg,h) ((((size_t)(dir)*BSZ + (b))*SSEG + (seg))*NHEADS + (h))
__device__ float g_hseg[(size_t)2 * BSZ * SSEG * NHEADS * HEADDIM * DSTATE];
__device__ float g_hin [(size_t)2 * BSZ * SSEG * NHEADS * HEADDIM * DSTATE];

// pre-split fp16 pair buffers
__device__ uint2 g_x2[(size_t)NTOK * (DMODEL / 2)];                // A fmt [m][kp]
__device__ uint2 g_fWin2[(size_t)(DMODEL / 2) * NPAD_WIN];         // B fmt [kp][n]
__device__ uint2 g_bWin2[(size_t)(DMODEL / 2) * NPAD_WIN];
__device__ uint2 g_fWout2[(size_t)(DINNER / 2) * DMODEL];
__device__ uint2 g_bWout2[(size_t)(DINNER / 2) * DMODEL];
__device__ uint2 g_Wo2[(size_t)DMODEL * DMODEL];
__device__ uint2 g_gn2[2][(size_t)NTOK * (DINNER / 2)];            // A fmt
__device__ uint2 g_cat2[(size_t)NTOK * DMODEL];                    // A fmt
// split-K partial buffers
#define PART_SZ ((size_t)NTOK * DMODEL)
__device__ float g_opart[4 * PART_SZ];   // out-proj: (dir,khalf)
__device__ float g_fpart[2 * PART_SZ];   // final: (khalf)

// ---------------- pre-split kernels ----------------
__global__ __launch_bounds__(256)
void presplitA(const float* __restrict__ in, uint2* __restrict__ out, int total)
{
    int t = (blockIdx.x * 256 + threadIdx.x) * 2;
    if (t >= total) return;
    float4 v = *(const float4*)(in + (size_t)t * 2);
    out[t]     = split2_f16(v.x, v.y);
    out[t + 1] = split2_f16(v.z, v.w);
}
__global__ __launch_bounds__(256)
void presplitB_all(const float* __restrict__ fWin, const float* __restrict__ bWin,
                   const float* __restrict__ fWout, const float* __restrict__ bWout,
                   const float* __restrict__ Wo,
                   uint2* __restrict__ o0, uint2* __restrict__ o1,
                   uint2* __restrict__ o2, uint2* __restrict__ o3,
                   uint2* __restrict__ o4)
{
    const int job = blockIdx.z;
    const int kp = blockIdx.y;
    const int n = blockIdx.x * 256 + threadIdx.x;
    const float* in; uint2* out; int N, Npad, KP;
    switch (job) {
        case 0: in = fWin;  out = o0; N = DPROJ;  Npad = NPAD_WIN; KP = DMODEL / 2; break;
        case 1: in = bWin;  out = o1; N = DPROJ;  Npad = NPAD_WIN; KP = DMODEL / 2; break;
        case 2: in = fWout; out = o2; N = DMODEL; Npad = DMODEL;   KP = DINNER / 2; break;
        case 3: in = bWout; out = o3; N = DMODEL; Npad = DMODEL;   KP = DINNER / 2; break;
        default: in = Wo;   out = o4; N = DMODEL; Npad = DMODEL;   KP = DMODEL;     break;
    }
    if (kp >= KP || n >= Npad) return;
    float v0 = 0.f, v1 = 0.f;
    if (n < N) {
        v0 = in[(size_t)(2 * kp) * N + n];
        v1 = in[(size_t)(2 * kp + 1) * N + n];
    }
    out[(size_t)kp * Npad + n] = split2_f16(v0, v1);
}

// ------ 2xFP16 tensor GEMM on pre-split pairs, split-K capable ----------------
#define PADU 132

__global__ __launch_bounds__(256, 2)
void tgemm_p(const uint2* __restrict__ A0, const uint2* __restrict__ A1, int lda2,
             const uint2* __restrict__ B0, const uint2* __restrict__ B1, int ldb2,
             float* __restrict__ C0, float* __restrict__ C1,
             uint2* __restrict__ P0, uint2* __restrict__ P1,
             float* __restrict__ PartBase,
             int ldc, int cco0, int cco1,
             int N, int K, int ksplit, int revA_mask, int revC_mask,
             const float* __restrict__ bias)
{
    __shared__ uint2 A2[2][8][PADU];
    __shared__ uint2 B2[2][8][PADU];

    const int zi = blockIdx.z;
    const int z = zi / ksplit;
    const int kh = zi % ksplit;
    const int K2h = K / (2 * ksplit);
    const uint2* Ag = z ? A1 : A0;
    const uint2* Bg = z ? B1 : B0;
    float* Cg = z ? C1 : C0;
    uint2* Pg = z ? P1 : P0;
    const int cco = z ? cco1 : cco0;
    const int revA = (revA_mask >> z) & 1;
    const int revC = (revC_mask >> z) & 1;

    const int tid = threadIdx.x;
    const int bn = blockIdx.x * 128;
    const int bm = blockIdx.y * 128;

    const int wid = tid >> 5;
    const int lane = tid & 31;
    const int warp_n = wid & 3;
    const int fg = lane >> 2;
    const int fc = lane & 3;
    const int m_warp = (wid >> 2) * 64;
    const int n_warp = warp_n * 32;

    const int a_row = tid >> 1;
    const int a_kp0 = (tid & 1) * 4;
    int am = bm + a_row;
    if (revA) { int bb = am >> 10; int ll = am & 1023; am = (bb << 10) + (1023 - ll); }
    const uint2* Ap = Ag + (size_t)am * lda2 + a_kp0 + kh * K2h;

    const int b_kp = tid >> 5;
    const int b_n0 = (tid & 31) * 4;
    const uint2* Bp = Bg + (size_t)(kh * K2h + b_kp) * ldb2 + bn + b_n0;

    float acc[4][4][4];
#pragma unroll
    for (int i = 0; i < 4; i++)
#pragma unroll
        for (int j = 0; j < 4; j++)
#pragma unroll
            for (int r = 0; r < 4; r++) acc[i][j][r] = 0.f;

    const int nk = K / (16 * ksplit);

    // ---- prologue ----
    {
        uint4 a01 = *(const uint4*)(Ap);
        uint4 a23 = *(const uint4*)(Ap + 2);
        A2[0][a_kp0 + 0][a_row] = make_uint2(a01.x, a01.y);
        A2[0][a_kp0 + 1][a_row] = make_uint2(a01.z, a01.w);
        A2[0][a_kp0 + 2][a_row] = make_uint2(a23.x, a23.y);
        A2[0][a_kp0 + 3][a_row] = make_uint2(a23.z, a23.w);
        uint4 b01 = *(const uint4*)(Bp);
        uint4 b23 = *(const uint4*)(Bp + 2);
        *(uint4*)&B2[0][b_kp][b_n0]     = b01;
        *(uint4*)&B2[0][b_kp][b_n0 + 2] = b23;
    }
    __syncthreads();

    for (int it = 0; it < nk; it++) {
        const int buf = it & 1;

        uint4 a01, a23, b01, b23;
        const bool more = (it + 1) < nk;
        if (more) {
            int kp8 = (it + 1) * 8;
            a01 = *(const uint4*)(Ap + kp8);
            a23 = *(const uint4*)(Ap + kp8 + 2);
            b01 = *(const uint4*)(Bp + (size_t)kp8 * ldb2);
            b23 = *(const uint4*)(Bp + (size_t)kp8 * ldb2 + 2);
        }

        {
            u32 bfrag[4][2];
#pragma unroll
            for (int in = 0; in < 4; in++) {
                int n = n_warp + in * 8 + fg;
                bfrag[in][0] = B2[buf][fc][n].x;
                bfrag[in][1] = B2[buf][fc + 4][n].x;
            }
#pragma unroll
            for (int im = 0; im < 4; im++) {
                int m0 = m_warp + im * 16 + fg;
                uint2 a00 = A2[buf][fc][m0];
                uint2 a01r = A2[buf][fc][m0 + 8];
                uint2 a10 = A2[buf][fc + 4][m0];
                uint2 a11 = A2[buf][fc + 4][m0 + 8];
                u32 ah[4] = {a00.x, a01r.x, a10.x, a11.x};
                u32 al[4] = {a00.y, a01r.y, a10.y, a11.y};
#pragma unroll
                for (int in = 0; in < 4; in++) {
                    mma_f16(acc[im][in], ah, bfrag[in]);   // hi*hi
                    mma_f16(acc[im][in], al, bfrag[in]);   // lo*hi
                }
            }
        }

        if (more) {
            const int nb = buf ^ 1;
            A2[nb][a_kp0 + 0][a_row] = make_uint2(a01.x, a01.y);
            A2[nb][a_kp0 + 1][a_row] = make_uint2(a01.z, a01.w);
            A2[nb][a_kp0 + 2][a_row] = make_uint2(a23.x, a23.y);
            A2[nb][a_kp0 + 3][a_row] = make_uint2(a23.z, a23.w);
            *(uint4*)&B2[nb][b_kp][b_n0]     = b01;
            *(uint4*)&B2[nb][b_kp][b_n0 + 2] = b23;
        }
        __syncthreads();
    }

    // ---- epilogue ----
#pragma unroll
    for (int im = 0; im < 4; im++) {
        int mrow0 = bm + m_warp + im * 16 + fg;
        int mrow1 = mrow0 + 8;
        int w0 = mrow0, w1 = mrow1;
        if (revC) {
            int bb = mrow0 >> 10, ll = mrow0 & 1023; w0 = (bb << 10) + (1023 - ll);
            bb = mrow1 >> 10; ll = mrow1 & 1023; w1 = (bb << 10) + (1023 - ll);
        }
        if (PartBase) {
            float* Q0 = PartBase + (size_t)zi * PART_SZ + (size_t)w0 * ldc;
            float* Q1 = PartBase + (size_t)zi * PART_SZ + (size_t)w1 * ldc;
#pragma unroll
            for (int in = 0; in < 4; in++) {
                int n0 = bn + n_warp + in * 8 + fc * 2;
                if (n0 < N)     { Q0[n0]     = acc[im][in][0]; }
                if (n0 + 1 < N) { Q0[n0 + 1] = acc[im][in][1]; }
                if (n0 < N)     { Q1[n0]     = acc[im][in][2]; }
                if (n0 + 1 < N) { Q1[n0 + 1] = acc[im][in][3]; }
            }
        } else if (Pg) {
            const int ldp = ldc >> 1;
            uint2* P0r = Pg + (size_t)w0 * ldp;
            uint2* P1r = Pg + (size_t)w1 * ldp;
#pragma unroll
            for (int in = 0; in < 4; in++) {
                int n0 = bn + n_warp + in * 8 + fc * 2;
                if (n0 + 1 <= N) {
                    int pc = (cco + n0) >> 1;
                    P0r[pc] = split2_f16(acc[im][in][0], acc[im][in][1]);
                    P1r[pc] = split2_f16(acc[im][in][2], acc[im][in][3]);
                }
            }
        } else {
            float* C0r = Cg + (size_t)w0 * ldc + cco;
            float* C1r = Cg + (size_t)w1 * ldc + cco;
#pragma unroll
            for (int in = 0; in < 4; in++) {
                int n0 = bn + n_warp + in * 8 + fc * 2;
                float b0 = 0.f, b1 = 0.f;
                if (bias) {
                    if (n0 < N) b0 = bias[n0];
                    if (n0 + 1 < N) b1 = bias[n0 + 1];
                }
                if (n0 < N)     { C0r[n0]     = acc[im][in][0] + b0; }
                if (n0 + 1 < N) { C0r[n0 + 1] = acc[im][in][1] + b1; }
                if (n0 < N)     { C1r[n0]     = acc[im][in][2] + b0; }
                if (n0 + 1 < N) { C1r[n0 + 1] = acc[im][in][3] + b1; }
            }
        }
    }
}

// ---- split-K reduce: out-proj partials -> cat2 fp16 pairs --------------------
__global__ __launch_bounds__(256)
void reduce_out()
{
    const int dir = blockIdx.y;
    const int row = blockIdx.x;
    const float* p0 = g_opart + (size_t)(dir * 2 + 0) * PART_SZ + (size_t)row * DMODEL;
    const float* p1 = g_opart + (size_t)(dir * 2 + 1) * PART_SZ + (size_t)row * DMODEL;
    uint2* o = g_cat2 + (size_t)row * DMODEL + dir * (DMODEL / 2) + threadIdx.x * 2;
    const int c0 = threadIdx.x * 4;
    float4 a = *(const float4*)&p0[c0];
    float4 b = *(const float4*)&p1[c0];
    o[0] = split2_f16(a.x + b.x, a.y + b.y);
    o[1] = split2_f16(a.z + b.z, a.w + b.w);
}

// ---- split-K reduce: final partials + bias -> out -----------------------------
__global__ __launch_bounds__(256)
void reduce_fin(float* __restrict__ out, const float* __restrict__ bias)
{
    const int row = blockIdx.x;
    const float* p0 = g_fpart + (size_t)row * DMODEL;
    const float* p1 = g_fpart + PART_SZ + (size_t)row * DMODEL;
    const int c0 = threadIdx.x * 4;
    float4 a = *(const float4*)&p0[c0];
    float4 b = *(const float4*)&p1[c0];
    float4 bb = *(const float4*)&bias[c0];
    float4 r;
    r.x = a.x + b.x + bb.x;
    r.y = a.y + b.y + bb.y;
    r.z = a.z + b.z + bb.z;
    r.w = a.w + b.w + bb.w;
    *(float4*)&out[(size_t)row * DMODEL + c0] = r;
}

// ---------------- conv (float4 vectorized) + silu + dt/dA ---------------------
__global__ __launch_bounds__(256)
void conv_silu_dt(const float* __restrict__ cw0, const float* __restrict__ cb0,
                  const float* __restrict__ dtb0, const float* __restrict__ Al0,
                  const float* __restrict__ cw1, const float* __restrict__ cb1,
                  const float* __restrict__ dtb1, const float* __restrict__ Al1)
{
    const int dir = blockIdx.z;
    const int b = blockIdx.y;
    const int l = blockIdx.x;
    const float* cw  = dir ? cw1  : cw0;
    const float* cb  = dir ? cb1  : cb0;
    const float* dtb = dir ? dtb1 : dtb0;
    const float* Al  = dir ? Al1  : Al0;

    const float* zx = g_zx[dir];
    const int row = b * LSEQ + l;
    float* out = g_xbc[dir] + (size_t)row * CONVCH;

    for (int c4 = threadIdx.x; c4 < CONVCH / 4; c4 += 256) {
        const int c = c4 * 4;
        float4 acc = *(const float4*)&cb[c];
#pragma unroll
        for (int j = 0; j < 4; j++) {
            int ls = l - 3 + j;
            if (ls >= 0) {
                float4 w = *(const float4*)&cw[j * CONVCH + c];
                float4 v = *(const float4*)&zx[(size_t)(b * LSEQ + ls) * DPROJ + DINNER + c];
                acc.x = fmaf(w.x, v.x, acc.x);
                acc.y = fmaf(w.y, v.y, acc.y);
                acc.z = fmaf(w.z, v.z, acc.z);
                acc.w = fmaf(w.w, v.w, acc.w);
            }
        }
        float4 o;
        o.x = acc.x * (1.f / (1.f + expf(-acc.x)));
        o.y = acc.y * (1.f / (1.f + expf(-acc.y)));
        o.z = acc.z * (1.f / (1.f + expf(-acc.z)));
        o.w = acc.w * (1.f / (1.f + expf(-acc.w)));
        *(float4*)&out[c] = o;
    }

    for (int h = threadIdx.x; h < NHEADS; h += 256) {
        float v = zx[(size_t)row * DPROJ + DINNER + CONVCH + h] + dtb[h];
        float dt = (v > 20.f) ? v : log1pf(expf(v));
        g_dt[dir][row * NHEADS + h] = dt;
        g_dA[dir][row * NHEADS + h] = expf(-expf(Al[h]) * dt);
    }
}

// ---------------- warp-level 64x64x64 3xTF32 GEMM helper (ssd) ----------------
template<int AK, int BK>
__device__ __forceinline__ void wgemm64(float (*acc)[4], const float* As, const float* Bm,
                                        int m0, int n0w, int fg, int fc)
{
#pragma unroll
    for (int k0 = 0; k0 < 64; k0 += 8) {
        u32 bh[4][2], bl[4][2];
#pragma unroll
        for (int in = 0; in < 4; in++) {
            int n = n0w + in * 8 + fg;
            float v0 = BK ? Bm[(k0 + fc) * 72 + n]     : Bm[n * 72 + k0 + fc];
            float v1 = BK ? Bm[(k0 + fc + 4) * 72 + n] : Bm[n * 72 + k0 + fc + 4];
            split_tf32(v0, bh[in][0], bl[in][0]);
            split_tf32(v1, bh[in][1], bl[in][1]);
        }
        float av0 = AK ? As[(k0 + fc) * 72 + m0 + fg]       : As[(m0 + fg) * 72 + k0 + fc];
        float av1 = AK ? As[(k0 + fc) * 72 + m0 + fg + 8]   : As[(m0 + fg + 8) * 72 + k0 + fc];
        float av2 = AK ? As[(k0 + fc + 4) * 72 + m0 + fg]   : As[(m0 + fg) * 72 + k0 + fc + 4];
        float av3 = AK ? As[(k0 + fc + 4) * 72 + m0 + fg + 8] : As[(m0 + fg + 8) * 72 + k0 + fc + 4];
        u32 ah[4], al[4];
        split_tf32(av0, ah[0], al[0]);
        split_tf32(av1, ah[1], al[1]);
        split_tf32(av2, ah[2], al[2]);
        split_tf32(av3, ah[3], al[3]);
#pragma unroll
        for (int in = 0; in < 4; in++) {
            mma_tf32(acc[in], ah, bh[in]);
            mma_tf32(acc[in], al, bh[in]);
            mma_tf32(acc[in], ah, bl[in]);
        }
    }
}

// ---------------- SSD pass 1 ----------------
__global__ __launch_bounds__(256)
void ssd_state()
{
    const int h = blockIdx.x;
    const int b = blockIdx.y / SSEG;
    const int ch = blockIdx.y % SSEG;
    const int dir = blockIdx.z;
    const int tid = threadIdx.x;
    const int t0 = b * LSEQ + ch * TSEG;
    const float* xbc = g_xbc[dir];

    __shared__ float Bs[64 * 72];
    __shared__ float Xs[64 * 72];
    __shared__ float das[64], dts_[64], w_[64], ahat_[64];

    for (int i = tid; i < 1024; i += 256) {
        int r = i >> 4, c4 = (i & 15) * 4;
        size_t row = (size_t)(t0 + r) * CONVCH;
        *(float4*)&Bs[r * 72 + c4] = *(const float4*)&xbc[row + DINNER + c4];
        *(float4*)&Xs[r * 72 + c4] = *(const float4*)&xbc[row + h * HEADDIM + c4];
    }
    if (tid < 64) {
        das[tid]  = g_dA[dir][(size_t)(t0 + tid) * NHEADS + h];
        dts_[tid] = g_dt[dir][(size_t)(t0 + tid) * NHEADS + h];
    }
    __syncthreads();
    if (tid == 0) {
        float acc = 1.f;
        for (int t = 0; t < 64; t++) { acc *= das[t]; ahat_[t] = acc; }
        float suf = 1.f;
        for (int s = 63; s >= 0; s--) { w_[s] = dts_[s] * suf; suf *= das[s]; }
    }
    __syncthreads();
    if (tid < 64)
        g_cump[dir][(size_t)(t0 + tid) * NHEADS + h] = ahat_[tid];
    for (int i = tid; i < 4096; i += 256) {
        int s = i >> 6, n = i & 63;
        Bs[s * 72 + n] *= w_[s];
    }
    __syncthreads();

    const int wid = tid >> 5, lane = tid & 31, fg = lane >> 2, fc = lane & 3;
    const int m0 = (wid & 3) * 16, n0w = (wid >> 2) * 32;
    float acc[4][4];
#pragma unroll
    for (int i = 0; i < 4; i++)
#pragma unroll
        for (int j = 0; j < 4; j++) acc[i][j] = 0.f;
    wgemm64<1, 1>(acc, Bs, Xs, m0, n0w, fg, fc);

    float* hd = g_hseg + SEGIDX(dir, b, ch, h) * (size_t)(HEADDIM * DSTATE);
#pragma unroll
    for (int in = 0; in < 4; in++) {
        int p = n0w + in * 8 + 2 * fc;
        hd[(m0 + fg) * 64 + p]     = acc[in][0];
        hd[(m0 + fg) * 64 + p + 1] = acc[in][1];
        hd[(m0 + fg + 8) * 64 + p]     = acc[in][2];
        hd[(m0 + fg + 8) * 64 + p + 1] = acc[in][3];
    }
}

// ---------------- SSD pass 2 ----------------
__global__ __launch_bounds__(256)
void ssd_combine()
{
    const int h = blockIdx.x;
    const int b = blockIdx.y;
    const int dir = blockIdx.z;
    const int tid = threadIdx.x;
    const int off = tid * 16;

    float hr[16];
#pragma unroll
    for (int i = 0; i < 16; i++) hr[i] = 0.f;

    for (int seg = 0; seg < SSEG; seg++) {
        size_t base = SEGIDX(dir, b, seg, h) * (size_t)(HEADDIM * DSTATE) + off;
        float* hin = g_hin + base;
#pragma unroll
        for (int i = 0; i < 16; i++) hin[i] = hr[i];
        float aend = g_cump[dir][(size_t)(b * LSEQ + seg * TSEG + TSEG - 1) * NHEADS + h];
        const float* hend = g_hseg + base;
#pragma unroll
        for (int i = 0; i < 16; i++) hr[i] = fmaf(aend, hr[i], hend[i]);
    }
}

// ---------------- SSD pass 3 ----------------
__global__ __launch_bounds__(256)
void ssd_y(const float* __restrict__ D0, const float* __restrict__ D1)
{
    extern __shared__ float sm[];
    float* Cs  = sm;
    float* Bsm = sm + 4608;
    float* Xs  = sm + 2 * 4608;
    float* Hs  = sm + 3 * 4608;
    float* Ms  = sm + 4 * 4608;
    __shared__ float das[64], dts_[64], ahat_[64];

    const int h = blockIdx.x;
    const int b = blockIdx.y / SSEG;
    const int ch = blockIdx.y % SSEG;
    const int dir = blockIdx.z;
    const int tid = threadIdx.x;
    const int t0 = b * LSEQ + ch * TSEG;
    const float* xbc = g_xbc[dir];
    const float Dh = (dir ? D1 : D0)[h];

    for (int i = tid; i < 1024; i += 256) {
        int r = i >> 4, c4 = (i & 15) * 4;
        size_t row = (size_t)(t0 + r) * CONVCH;
        *(float4*)&Bsm[r * 72 + c4] = *(const float4*)&xbc[row + DINNER + c4];
        *(float4*)&Cs [r * 72 + c4] = *(const float4*)&xbc[row + DINNER + DSTATE + c4];
        *(float4*)&Xs [r * 72 + c4] = *(const float4*)&xbc[row + h * HEADDIM + c4];
    }
    {
        const float* hin = g_hin + SEGIDX(dir, b, ch, h) * (size_t)(HEADDIM * DSTATE);
        for (int i = tid; i < 1024; i += 256) {
            int r = i >> 4, c4 = (i & 15) * 4;
            *(float4*)&Hs[r * 72 + c4] = *(const float4*)&hin[r * 64 + c4];
        }
    }
    if (tid < 64) {
        das[tid]  = g_dA[dir][(size_t)(t0 + tid) * NHEADS + h];
        dts_[tid] = g_dt[dir][(size_t)(t0 + tid) * NHEADS + h];
        ahat_[tid] = g_cump[dir][(size_t)(t0 + tid) * NHEADS + h];
    }
    for (int i = tid; i < 4608; i += 256) Ms[i] = 0.f;
    __syncthreads();

    if (tid < 64) {
        int s = tid;
        float m = dts_[s];
        Ms[s * 72 + s] = m;
        for (int t = s + 1; t < 64; t++) {
            m *= das[t];
            Ms[t * 72 + s] = m;
        }
    }
    __syncthreads();

    const int wid = tid >> 5, lane = tid & 31, fg = lane >> 2, fc = lane & 3;
    const int m0 = (wid & 3) * 16, n0w = (wid >> 2) * 32;

    float accg[4][4];
#pragma unroll
    for (int i = 0; i < 4; i++)
#pragma unroll
        for (int j = 0; j < 4; j++) accg[i][j] = 0.f;
    wgemm64<0, 0>(accg, Cs, Bsm, m0, n0w, fg, fc);
    __syncthreads();

#pragma unroll
    for (int in = 0; in < 4; in++) {
        int s = n0w + in * 8 + 2 * fc;
        int t = m0 + fg;
        Bsm[t * 72 + s]     = accg[in][0] * Ms[t * 72 + s];
        Bsm[t * 72 + s + 1] = accg[in][1] * Ms[t * 72 + s + 1];
        Bsm[(t + 8) * 72 + s]     = accg[in][2] * Ms[(t + 8) * 72 + s];
        Bsm[(t + 8) * 72 + s + 1] = accg[in][3] * Ms[(t + 8) * 72 + s + 1];
    }
    for (int i = tid; i < 4096; i += 256) {
        int t = i >> 6, n = i & 63;
        Cs[t * 72 + n] *= ahat_[t];
    }
    __syncthreads();

    float accy[4][4];
#pragma unroll
    for (int i = 0; i < 4; i++)
#pragma unroll
        for (int j = 0; j < 4; j++) accy[i][j] = 0.f;
    wgemm64<0, 1>(accy, Bsm, Xs, m0, n0w, fg, fc);
    wgemm64<0, 1>(accy, Cs, Hs, m0, n0w, fg, fc);

    float* yout = g_y[dir];
#pragma unroll
    for (int in = 0; in < 4; in++) {
        int p = n0w + in * 8 + 2 * fc;
#pragma unroll
        for (int rr = 0; rr < 2; rr++) {
            int t = m0 + fg + rr * 8;
            float x0 = Xs[t * 72 + p];
            float x1 = Xs[t * 72 + p + 1];
            size_t idx = (size_t)(t0 + t) * DINNER + h * HEADDIM + p;
            yout[idx]     = accy[in][2 * rr + 0] + Dh * x0;
            yout[idx + 1] = accy[in][2 * rr + 1] + Dh * x1;
        }
    }
}

// -------- gated RMSNorm: emits pre-split fp16 pairs directly ------------------
__global__ __launch_bounds__(256)
void gated_norm(const float* __restrict__ nw0, const float* __restrict__ nw1)
{
    const int dir = blockIdx.y;
    const int row = blockIdx.x;
    const float* nw = dir ? nw1 : nw0;
    const float* y = g_y[dir] + (size_t)row * DINNER;
    const float* z = g_zx[dir] + (size_t)row * DPROJ;
    uint2* o = g_gn2[dir] + (size_t)row * (DINNER / 2) + threadIdx.x * 4;

    const int c0 = threadIdx.x * 8;
    float4 y0 = *(const float4*)&y[c0];
    float4 y1 = *(const float4*)&y[c0 + 4];
    float4 z0 = *(const float4*)&z[c0];
    float4 z1 = *(const float4*)&z[c0 + 4];
    float g[8];
    g[0] = y0.x * (z0.x / (1.f + expf(-z0.x)));
    g[1] = y0.y * (z0.y / (1.f + expf(-z0.y)));
    g[2] = y0.z * (z0.z / (1.f + expf(-z0.z)));
    g[3] = y0.w * (z0.w / (1.f + expf(-z0.w)));
    g[4] = y1.x * (z1.x / (1.f + expf(-z1.x)));
    g[5] = y1.y * (z1.y / (1.f + expf(-z1.y)));
    g[6] = y1.z * (z1.z / (1.f + expf(-z1.z)));
    g[7] = y1.w * (z1.w / (1.f + expf(-z1.w)));
    float ss = 0.f;
#pragma unroll
    for (int i = 0; i < 8; i++) ss = fmaf(g[i], g[i], ss);
#pragma unroll
    for (int o2 = 16; o2; o2 >>= 1) ss += __shfl_xor_sync(0xffffffffu, ss, o2);
    __shared__ float red[8];
    if ((threadIdx.x & 31) == 0) red[threadIdx.x >> 5] = ss;
    __syncthreads();
    float tot = red[0] + red[1] + red[2] + red[3] + red[4] + red[5] + red[6] + red[7];
    float scale = rsqrtf(tot * (1.f / DINNER) + 1e-5f);

    float4 w0 = *(const float4*)&nw[c0];
    float4 w1 = *(const float4*)&nw[c0 + 4];
    float v[8];
    v[0] = g[0] * scale * w0.x; v[1] = g[1] * scale * w0.y;
    v[2] = g[2] * scale * w0.z; v[3] = g[3] * scale * w0.w;
    v[4] = g[4] * scale * w1.x; v[5] = g[5] * scale * w1.y;
    v[6] = g[6] * scale * w1.z; v[7] = g[7] * scale * w1.w;
    o[0] = split2_f16(v[0], v[1]);
    o[1] = split2_f16(v[2], v[3]);
    o[2] = split2_f16(v[4], v[5]);
    o[3] = split2_f16(v[6], v[7]);
}

// ---------------- launch ----------------
extern "C" void kernel_launch(void* const* d_in, const int* in_sizes, int n_in,
                              void* d_out, int out_size)
{
    (void)in_sizes; (void)n_in; (void)out_size;
    const float* x      = (const float*)d_in[0];
    const float* fWin   = (const float*)d_in[1];
    const float* fconvw = (const float*)d_in[2];
    const float* fconvb = (const float*)d_in[3];
    const float* fdtb   = (const float*)d_in[4];
    const float* fAlog  = (const float*)d_in[5];
    const float* fD     = (const float*)d_in[6];
    const float* fnormw = (const float*)d_in[7];
    const float* fWout  = (const float*)d_in[8];
    const float* bWin   = (const float*)d_in[9];
    const float* bconvw = (const float*)d_in[10];
    const float* bconvb = (const float*)d_in[11];
    const float* bdtb   = (const float*)d_in[12];
    const float* bAlog  = (const float*)d_in[13];
    const float* bD     = (const float*)d_in[14];
    const float* bnormw = (const float*)d_in[15];
    const float* bWout  = (const float*)d_in[16];
    const float* Wo     = (const float*)d_in[17];
    const float* bo     = (const float*)d_in[18];
    float* out = (float*)d_out;

    static int smem_set = 0;
    if (!smem_set) {
        cudaFuncSetAttribute(ssd_y, cudaFuncAttributeMaxDynamicSharedMemorySize, 5 * 4608 * 4);
        smem_set = 1;
    }

    float* zx;
    uint2 *x2, *fWin2, *bWin2, *fWout2, *bWout2, *Wo2, *gn2, *cat2;
    cudaGetSymbolAddress((void**)&zx, g_zx);
    cudaGetSymbolAddress((void**)&x2, g_x2);
    cudaGetSymbolAddress((void**)&fWin2, g_fWin2);
    cudaGetSymbolAddress((void**)&bWin2, g_bWin2);
    cudaGetSymbolAddress((void**)&fWout2, g_fWout2);
    cudaGetSymbolAddress((void**)&bWout2, g_bWout2);
    cudaGetSymbolAddress((void**)&Wo2, g_Wo2);
    cudaGetSymbolAddress((void**)&gn2, g_gn2);
    cudaGetSymbolAddress((void**)&cat2, g_cat2);
    float* opart;
    float* fpart;
    cudaGetSymbolAddress((void**)&opart, g_opart);
    cudaGetSymbolAddress((void**)&fpart, g_fpart);
    float* zx0 = zx;
    float* zx1 = zx + (size_t)NTOK * DPROJ;
    uint2* gn2_0 = gn2;
    uint2* gn2_1 = gn2 + (size_t)NTOK * (DINNER / 2);

    // 0) pre-split x and weights to fp16 pairs
    presplitA<<<(NTOK * (DMODEL / 2) / 2 + 255) / 256, 256>>>(x, x2, NTOK * (DMODEL / 2));
    presplitB_all<<<dim3(17, 1024, 5), 256>>>(fWin, bWin, fWout, bWout, Wo,
                                              fWin2, bWin2, fWout2, bWout2, Wo2);

    // 1) input projections (merged dirs; dir1 reads x reversed)
    tgemm_p<<<dim3(NPAD_WIN / 128, NTOK / 128, 2), 256>>>(
        x2, x2, DMODEL / 2, fWin2, bWin2, NPAD_WIN,
        zx0, zx1, nullptr, nullptr, nullptr, DPROJ, 0, 0,
        DPROJ, DMODEL, 1, /*revA*/0b10, /*revC*/0, nullptr);

    // 2) causal conv + silu + dt/dA
    conv_silu_dt<<<dim3(LSEQ, BSZ, 2), 256>>>(fconvw, fconvb, fdtb, fAlog,
                                              bconvw, bconvb, bdtb, bAlog);

    // 3) SSD tensor-core scan
    ssd_state<<<dim3(NHEADS, BSZ * SSEG, 2), 256>>>();
    ssd_combine<<<dim3(NHEADS, BSZ, 2), 256>>>();
    ssd_y<<<dim3(NHEADS, BSZ * SSEG, 2), 256, 5 * 4608 * 4>>>(fD, bD);

    // 4) gated RMSNorm -> fp16 pairs
    gated_norm<<<dim3(NTOK, 2), 256>>>(fnormw, bnormw);

    // 5) out projections, split-K=2 over both dirs -> fp32 partials, then
    //    reduce into cat2 pairs (dir1 rows flipped back by the GEMM's revC)
    tgemm_p<<<dim3(DMODEL / 128, NTOK / 128, 4), 256>>>(
        gn2_0, gn2_1, DINNER / 2, fWout2, bWout2, DMODEL,
        nullptr, nullptr, nullptr, nullptr, opart, DMODEL, 0, 0,
        DMODEL, DINNER, 2, /*revA*/0, /*revC*/0b10, nullptr);
    reduce_out<<<dim3(NTOK, 2), 256>>>();

    // 6) final projection, split-K=2 -> partials, then reduce + bias
    tgemm_p<<<dim3(DMODEL / 128, NTOK / 128, 2), 256>>>(
        cat2, cat2, DMODEL, Wo2, Wo2, DMODEL,
        nullptr, nullptr, nullptr, nullptr, fpart, DMODEL, 0, 0,
        DMODEL, 2 * DMODEL, 2, 0, 0, nullptr);
    reduce_fin<<<NTOK, 256>>>(out, bo);
}